// round 5
// baseline (speedup 1.0000x reference)
#include <cuda_runtime.h>
#include <math.h>
#include <stdint.h>

#define BATCH 128
#define SEQ   40
#define HID   512
#define EMB   512
#define VOC   10000
#define FCF   2048
#define GATE4 2048            // 4*HID
#define MTOT  (BATCH*SEQ)     // 5120

// ---------------- workspaces (static device globals; no allocation) --------
__device__ float g_XA[MTOT*GATE4];     // embed[word]@a_wih^T + a_bih + a_bhh
__device__ float g_XF[MTOT*GATE4];     // embed[word]@f_wih^T + f_bih + f_bhh
__device__ float g_X0[BATCH*EMB];      // fc_feats@fc_w^T + fc_b
__device__ float g_GATES[BATCH*2*GATE4]; // step-0 gates
__device__ float g_HCAT[MTOT*2*HID];   // [ch | bh] per (b,t)
__device__ float g_CS[MTOT*HID];       // ancestor cell state per (b,t)
__device__ float g_BC[MTOT*HID];       // sibling cell state per (b,t)
__device__ float g_OUT[MTOT*HID];      // tanh(pred) outputs
__device__ int   g_FIDX[MTOT];         // [t][b] -> b*SEQ + father_idx[b][t]
__device__ int   g_SIDX[MTOT];         // [t][b] -> b*SEQ + (t-1)
__device__ int   g_WIDX[MTOT];         // normalized word_idx ([b][t])
__device__ int   g_IS64;               // 1 if index inputs are int64

// ---------------- helpers ---------------------------------------------------
__device__ __forceinline__ float tf32r(float v) {
    unsigned u;
    asm("cvt.rna.tf32.f32 %0, %1;" : "=r"(u) : "f"(v));
    return __uint_as_float(u);
}

__device__ __forceinline__ void mma_tf32(float* c, const unsigned* a, const unsigned* b) {
    asm volatile(
        "mma.sync.aligned.m16n8k8.row.col.f32.tf32.tf32.f32 "
        "{%0,%1,%2,%3}, {%4,%5,%6,%7}, {%8,%9}, {%0,%1,%2,%3};"
        : "+f"(c[0]), "+f"(c[1]), "+f"(c[2]), "+f"(c[3])
        : "r"(a[0]), "r"(a[1]), "r"(a[2]), "r"(a[3]), "r"(b[0]), "r"(b[1]));
}

__device__ __forceinline__ float sigm(float x) { return 1.f / (1.f + expf(-x)); }

// ---------------- generic tf32 GEMM (batched phases) ------------------------
struct GemmP {
    const float* A;    int lda;   const int* aidx;
    const float* B;    int ldb;
    const float* Cadd; int ldcadd;
    float*       C;    int ldc;
    const float* bias1; const float* bias2;
    int M, N, K;
    int act;  // 0 = none, 1 = tanh
};

__device__ __forceinline__ void gstore(const GemmP& p, int m, int n, float v) {
    if (m < p.M && n < p.N) {
        if (p.Cadd) {
            int cr = p.aidx ? p.aidx[m] : m;
            v += p.Cadd[(long)cr * p.ldcadd + n];
        }
        if (p.bias1) v += p.bias1[n];
        if (p.bias2) v += p.bias2[n];
        if (p.act) v = tanhf(v);
        p.C[(long)m * p.ldc + n] = v;
    }
}

template<int BM, int BN, int BK, int WRM, int WRN>
__global__ void __launch_bounds__(WRM*WRN*32)
gemm_k(GemmP P0, GemmP P1) {
    const GemmP p = (blockIdx.z == 0) ? P0 : P1;
    constexpr int THREADS = WRM * WRN * 32;
    constexpr int BKP = BK + 4;
    constexpr int WM = BM / WRM, WN = BN / WRN;
    constexpr int MT = WM / 16, NT = WN / 8;

    __shared__ float sA[BM][BKP];
    __shared__ float sB[BN][BKP];

    const int tid  = threadIdx.x;
    const int warp = tid >> 5, lane = tid & 31;
    const int g = lane >> 2, tig = lane & 3;
    const int wm = warp % WRM, wn = warp / WRM;
    const int bm0 = blockIdx.y * BM, bn0 = blockIdx.x * BN;

    float acc[MT][NT][4];
    #pragma unroll
    for (int mt = 0; mt < MT; mt++)
        #pragma unroll
        for (int nt = 0; nt < NT; nt++)
            #pragma unroll
            for (int q = 0; q < 4; q++) acc[mt][nt][q] = 0.f;

    constexpr int TPR = BK / 4;
    constexpr int RPI = THREADS / TPR;
    const int lr = tid / TPR;
    const int lc = (tid % TPR) * 4;

    for (int k0 = 0; k0 < p.K; k0 += BK) {
        for (int r = lr; r < BM; r += RPI) {
            int m = bm0 + r;
            float4 v = make_float4(0.f, 0.f, 0.f, 0.f);
            if (m < p.M) {
                int row = p.aidx ? p.aidx[m] : m;
                v = *(const float4*)(p.A + (long)row * p.lda + k0 + lc);
            }
            sA[r][lc + 0] = tf32r(v.x);
            sA[r][lc + 1] = tf32r(v.y);
            sA[r][lc + 2] = tf32r(v.z);
            sA[r][lc + 3] = tf32r(v.w);
        }
        for (int r = lr; r < BN; r += RPI) {
            int n = bn0 + r;
            float4 v = make_float4(0.f, 0.f, 0.f, 0.f);
            if (n < p.N)
                v = *(const float4*)(p.B + (long)n * p.ldb + k0 + lc);
            sB[r][lc + 0] = tf32r(v.x);
            sB[r][lc + 1] = tf32r(v.y);
            sB[r][lc + 2] = tf32r(v.z);
            sB[r][lc + 3] = tf32r(v.w);
        }
        __syncthreads();

        #pragma unroll
        for (int kk = 0; kk < BK; kk += 8) {
            unsigned afr[MT][4];
            unsigned bfr[NT][2];
            #pragma unroll
            for (int mt = 0; mt < MT; mt++) {
                int mb = wm * WM + mt * 16;
                afr[mt][0] = __float_as_uint(sA[mb + g    ][kk + tig    ]);
                afr[mt][1] = __float_as_uint(sA[mb + g + 8][kk + tig    ]);
                afr[mt][2] = __float_as_uint(sA[mb + g    ][kk + tig + 4]);
                afr[mt][3] = __float_as_uint(sA[mb + g + 8][kk + tig + 4]);
            }
            #pragma unroll
            for (int nt = 0; nt < NT; nt++) {
                int nb = wn * WN + nt * 8;
                bfr[nt][0] = __float_as_uint(sB[nb + g][kk + tig    ]);
                bfr[nt][1] = __float_as_uint(sB[nb + g][kk + tig + 4]);
            }
            #pragma unroll
            for (int mt = 0; mt < MT; mt++)
                #pragma unroll
                for (int nt = 0; nt < NT; nt++)
                    mma_tf32(acc[mt][nt], afr[mt], bfr[nt]);
        }
        __syncthreads();
    }

    #pragma unroll
    for (int mt = 0; mt < MT; mt++) {
        int r0 = bm0 + wm * WM + mt * 16 + g;
        #pragma unroll
        for (int nt = 0; nt < NT; nt++) {
            int c0 = bn0 + wn * WN + nt * 8 + 2 * tig;
            gstore(p, r0,     c0,     acc[mt][nt][0]);
            gstore(p, r0,     c0 + 1, acc[mt][nt][1]);
            gstore(p, r0 + 8, c0,     acc[mt][nt][2]);
            gstore(p, r0 + 8, c0 + 1, acc[mt][nt][3]);
        }
    }
}

// ---------------- fused recurrent step kernel -------------------------------
// One block: 32 batch rows x 64 units, all 4 gates (effective N-tile 256).
// 256 threads = 8 warps in a 2(m) x 4(n) grid; each warp 16 rows x 64 cols.
// gates = h_gather @ W^T (MMA) + X[row]  (X already holds x-side + biases)
// then LSTM cell math in the epilogue; writes h and c directly.
struct StepP {
    const float* Abase;   // h source base (HCAT [+HID for f]); row = idx[m]*1024
    const int*   idx;     // [BATCH] source position per batch row
    const float* W;       // whh [2048, 512] gate-major
    const float* X;       // XA/XF base; row = idx[m]*2048 (biases folded in)
    const float* Cprev;   // CS/BC base; row = idx[m]*512
    float*       Hout;    // HCAT + t*1024 (+HID for f); + b*SEQ*1024 + u
    float*       Cout;    // CS/BC + t*512; + b*SEQ*512 + u
};

__global__ void __launch_bounds__(256) step_k(StepP Pa, StepP Pf) {
    const StepP p = blockIdx.z ? Pf : Pa;
    const int u0 = blockIdx.x * 64;
    const int b0 = blockIdx.y * 32;

    __shared__ float smem[32*36 + 256*36];      // sA | sB, reused as sG
    float (*sA)[36] = (float(*)[36])smem;
    float (*sB)[36] = (float(*)[36])(smem + 32*36);
    float (*sG)[260] = (float(*)[260])smem;     // 32*260 = 8320 < 10368
    __shared__ int sIdx[32];

    const int tid  = threadIdx.x;
    const int warp = tid >> 5, lane = tid & 31;
    const int g = lane >> 2, tig = lane & 3;
    const int wm = warp & 1, wn = warp >> 1;    // 2x4 warps; WM=16, WN=64

    if (tid < 32) sIdx[tid] = p.idx[b0 + tid];
    __syncthreads();

    float acc[8][4];
    #pragma unroll
    for (int nt = 0; nt < 8; nt++)
        #pragma unroll
        for (int q = 0; q < 4; q++) acc[nt][q] = 0.f;

    // loaders: TPR = 8 (32 cols / float4), RPI = 32
    const int lr = tid >> 3;
    const int lc = (tid & 7) * 4;

    for (int k0 = 0; k0 < 512; k0 += 32) {
        if (lr < 32) {
            float4 v = *(const float4*)(p.Abase + (long)sIdx[lr] * (2*HID) + k0 + lc);
            sA[lr][lc + 0] = tf32r(v.x);
            sA[lr][lc + 1] = tf32r(v.y);
            sA[lr][lc + 2] = tf32r(v.z);
            sA[lr][lc + 3] = tf32r(v.w);
        }
        #pragma unroll
        for (int r = lr; r < 256; r += 32) {
            int wrow = (r >> 6) * HID + u0 + (r & 63);
            float4 v = *(const float4*)(p.W + (long)wrow * HID + k0 + lc);
            sB[r][lc + 0] = tf32r(v.x);
            sB[r][lc + 1] = tf32r(v.y);
            sB[r][lc + 2] = tf32r(v.z);
            sB[r][lc + 3] = tf32r(v.w);
        }
        __syncthreads();

        #pragma unroll
        for (int kk = 0; kk < 32; kk += 8) {
            unsigned afr[4];
            const int mb = wm * 16;
            afr[0] = __float_as_uint(sA[mb + g    ][kk + tig    ]);
            afr[1] = __float_as_uint(sA[mb + g + 8][kk + tig    ]);
            afr[2] = __float_as_uint(sA[mb + g    ][kk + tig + 4]);
            afr[3] = __float_as_uint(sA[mb + g + 8][kk + tig + 4]);
            #pragma unroll
            for (int nt = 0; nt < 8; nt++) {
                unsigned bfr[2];
                const int nb = wn * 64 + nt * 8;
                bfr[0] = __float_as_uint(sB[nb + g][kk + tig    ]);
                bfr[1] = __float_as_uint(sB[nb + g][kk + tig + 4]);
                mma_tf32(acc[nt], afr, bfr);
            }
        }
        __syncthreads();
    }

    // stage gates to shared (overwrites sA/sB region)
    #pragma unroll
    for (int nt = 0; nt < 8; nt++) {
        const int m = wm * 16 + g;
        const int n = wn * 64 + nt * 8 + 2 * tig;
        sG[m    ][n    ] = acc[nt][0];
        sG[m    ][n + 1] = acc[nt][1];
        sG[m + 8][n    ] = acc[nt][2];
        sG[m + 8][n + 1] = acc[nt][3];
    }
    __syncthreads();

    // cell math: 2048 elements / 256 threads = 8 each
    #pragma unroll
    for (int e = tid; e < 2048; e += 256) {
        const int m = e >> 6, ul = e & 63;
        const int b = b0 + m, u = u0 + ul;
        const long xr = sIdx[m];
        const float* xp = p.X + xr * (long)GATE4;
        float gi = sG[m][ul      ] + xp[u            ];
        float gf = sG[m][64 + ul ] + xp[HID + u      ];
        float gg = sG[m][128 + ul] + xp[2 * HID + u  ];
        float go = sG[m][192 + ul] + xp[3 * HID + u  ];
        float cp = p.Cprev[xr * HID + u];
        float c2 = sigm(gf) * cp + sigm(gi) * tanhf(gg);
        float h  = sigm(go) * tanhf(c2);
        p.Hout[(long)b * (SEQ * 2 * HID) + u] = h;
        p.Cout[(long)b * (SEQ * HID) + u]     = c2;
    }
}

// ---------------- sibling reset (bias-only f-cell) --------------------------
__global__ void sib_reset(const float* fb1, const float* fb2, int t) {
    int i = blockIdx.x * blockDim.x + threadIdx.x;
    if (i >= BATCH * HID) return;
    int b = i >> 9, u = i & (HID - 1);
    float fi = fb1[u]           + fb2[u];
    float fg = fb1[2*HID + u]   + fb2[2*HID + u];
    float fo = fb1[3*HID + u]   + fb2[3*HID + u];
    float bc2 = sigm(fi) * tanhf(fg);       // cprev = 0
    float bh  = sigm(fo) * tanhf(bc2);
    long orow = (long)b * SEQ + t;
    g_HCAT[orow * (2 * HID) + HID + u] = bh;
    g_BC[orow * HID + u] = bc2;
}

// ---------------- index dtype sniff + normalization -------------------------
__global__ void sniff_idx(const int* word32) {
    if (threadIdx.x == 0) {
        int allzero = 1;
        for (int i = 0; i < 64; i++)
            if (word32[2 * i + 1] != 0) { allzero = 0; break; }
        g_IS64 = allzero;
    }
}

__global__ void prep_idx(const int* word32, const int* father32) {
    int i = blockIdx.x * blockDim.x + threadIdx.x;
    if (i >= MTOT) return;
    int is64 = g_IS64;
    int w = is64 ? word32[2 * i]   : word32[i];
    int f = is64 ? father32[2 * i] : father32[i];
    g_WIDX[i] = w;
    int t = i % SEQ, b = i / SEQ;
    g_FIDX[t * BATCH + b] = b * SEQ + f;
    g_SIDX[t * BATCH + b] = b * SEQ + (t > 0 ? t - 1 : 0);
}

// ---------------- step-0 LSTM elementwise (generic path) --------------------
__global__ void lstm_ew0(const float* fb1, const float* fb2) {
    int i = blockIdx.x * blockDim.x + threadIdx.x;
    if (i >= BATCH * HID) return;
    int b = i >> 9, u = i & (HID - 1);
    const float* ga = g_GATES + (long)b * (2 * GATE4);
    float gi = ga[u], gg = ga[2*HID + u], go = ga[3*HID + u];
    float c2 = sigm(gi) * tanhf(gg);        // cprev = 0
    float ch = sigm(go) * tanhf(c2);
    long orow = (long)b * SEQ;      // t = 0
    g_HCAT[orow * (2 * HID) + u] = ch;
    g_CS[orow * HID + u] = c2;
    // sibling: bias only
    float fi = fb1[u]         + fb2[u];
    float fg = fb1[2*HID + u] + fb2[2*HID + u];
    float fo = fb1[3*HID + u] + fb2[3*HID + u];
    float bc2 = sigm(fi) * tanhf(fg);
    float bh  = sigm(fo) * tanhf(bc2);
    g_HCAT[orow * (2 * HID) + HID + u] = bh;
    g_BC[orow * HID + u] = bc2;
}

// ---------------- in-place log_softmax over rows of 10000 -------------------
__global__ void logsoftmax_k(float* out) {
    const long row = blockIdx.x;
    float* p = out + row * (long)VOC;
    const int tid = threadIdx.x;
    __shared__ float sred[8];

    float v[40];
    float mx = -INFINITY;
    #pragma unroll
    for (int j = 0; j < 40; j++) {
        int idx = j * 256 + tid;
        v[j] = (idx < VOC) ? p[idx] : -INFINITY;
        mx = fmaxf(mx, v[j]);
    }
    #pragma unroll
    for (int o = 16; o > 0; o >>= 1)
        mx = fmaxf(mx, __shfl_xor_sync(0xffffffffu, mx, o));
    if ((tid & 31) == 0) sred[tid >> 5] = mx;
    __syncthreads();
    float mall = -INFINITY;
    #pragma unroll
    for (int w = 0; w < 8; w++) mall = fmaxf(mall, sred[w]);
    __syncthreads();

    float s = 0.f;
    #pragma unroll
    for (int j = 0; j < 40; j++) {
        int idx = j * 256 + tid;
        if (idx < VOC) s += expf(v[j] - mall);
    }
    #pragma unroll
    for (int o = 16; o > 0; o >>= 1)
        s += __shfl_xor_sync(0xffffffffu, s, o);
    if ((tid & 31) == 0) sred[tid >> 5] = s;
    __syncthreads();
    float stot = 0.f;
    #pragma unroll
    for (int w = 0; w < 8; w++) stot += sred[w];

    float lse = mall + logf(stot);
    #pragma unroll
    for (int j = 0; j < 40; j++) {
        int idx = j * 256 + tid;
        if (idx < VOC) p[idx] = v[j] - lse;
    }
}

// ---------------- host orchestration ---------------------------------------
extern "C" void kernel_launch(void* const* d_in, const int* in_sizes, int n_in,
                              void* d_out, int out_size) {
    const int*   word    = (const int*)  d_in[0];
    const int*   father  = (const int*)  d_in[1];
    const float* fc_feats= (const float*)d_in[2];
    const float* embed   = (const float*)d_in[3];
    const float* fc_w    = (const float*)d_in[4];
    const float* fc_b    = (const float*)d_in[5];
    const float* a_wih   = (const float*)d_in[6];
    const float* a_whh   = (const float*)d_in[7];
    const float* a_bih   = (const float*)d_in[8];
    const float* a_bhh   = (const float*)d_in[9];
    const float* f_wih   = (const float*)d_in[10];
    const float* f_whh   = (const float*)d_in[11];
    const float* f_bih   = (const float*)d_in[12];
    const float* f_bhh   = (const float*)d_in[13];
    const float* pred_w  = (const float*)d_in[14];
    const float* pred_b  = (const float*)d_in[15];
    const float* logit_w = (const float*)d_in[16];
    const float* logit_b = (const float*)d_in[17];
    float* out = (float*)d_out;

    float *XA, *XF, *X0, *GT, *HC, *CS, *BC, *OB;
    int *FIDX, *SIDX, *WIDX;
    cudaGetSymbolAddress((void**)&XA,  g_XA);
    cudaGetSymbolAddress((void**)&XF,  g_XF);
    cudaGetSymbolAddress((void**)&X0,  g_X0);
    cudaGetSymbolAddress((void**)&GT,  g_GATES);
    cudaGetSymbolAddress((void**)&HC,  g_HCAT);
    cudaGetSymbolAddress((void**)&CS,  g_CS);
    cudaGetSymbolAddress((void**)&BC,  g_BC);
    cudaGetSymbolAddress((void**)&OB,  g_OUT);
    cudaGetSymbolAddress((void**)&FIDX, g_FIDX);
    cudaGetSymbolAddress((void**)&SIDX, g_SIDX);
    cudaGetSymbolAddress((void**)&WIDX, g_WIDX);

    sniff_idx<<<1, 32>>>(word);
    prep_idx<<<(MTOT + 255) / 256, 256>>>(word, father);

    // X0 = fc_feats @ fc_w^T + fc_b            [128, 512], K=2048
    {
        GemmP p{}; p.A = fc_feats; p.lda = FCF; p.B = fc_w; p.ldb = FCF;
        p.C = X0; p.ldc = EMB; p.bias1 = fc_b;
        p.M = BATCH; p.N = EMB; p.K = FCF;
        gemm_k<32,64,32,1,2><<<dim3(EMB/64, BATCH/32, 1), 64>>>(p, p);
    }
    // XA/XF = embed[word] @ {a,f}_wih^T + biases   [5120, 2048], K=512 (z=2)
    {
        GemmP pa{}; pa.A = embed; pa.lda = EMB; pa.aidx = WIDX;
        pa.B = a_wih; pa.ldb = EMB; pa.C = XA; pa.ldc = GATE4;
        pa.bias1 = a_bih; pa.bias2 = a_bhh;
        pa.M = MTOT; pa.N = GATE4; pa.K = EMB;
        GemmP pf = pa;
        pf.B = f_wih; pf.C = XF; pf.bias1 = f_bih; pf.bias2 = f_bhh;
        gemm_k<128,128,32,4,2><<<dim3(GATE4/128, MTOT/128, 2), 256>>>(pa, pf);
    }
    // step 0 a-gates: GT = X0 @ a_wih^T + a_bih + a_bhh
    {
        GemmP p{}; p.A = X0; p.lda = EMB; p.B = a_wih; p.ldb = EMB;
        p.C = GT; p.ldc = 2 * GATE4; p.bias1 = a_bih; p.bias2 = a_bhh;
        p.M = BATCH; p.N = GATE4; p.K = EMB;
        gemm_k<32,64,32,1,2><<<dim3(GATE4/64, BATCH/32, 1), 64>>>(p, p);
    }
    lstm_ew0<<<(BATCH * HID + 255) / 256, 256>>>(f_bih, f_bhh);

    // recurrent steps (fused GEMM + cell)
    for (int t = 1; t < SEQ; t++) {
        int reset = ((t - 1) % 3 == 0) ? 1 : 0;

        StepP pa{};
        pa.Abase = HC;                 pa.idx = FIDX + t * BATCH;
        pa.W = a_whh;                  pa.X = XA;
        pa.Cprev = CS;
        pa.Hout = HC + (long)t * (2 * HID);
        pa.Cout = CS + (long)t * HID;

        StepP pf{};
        pf.Abase = HC + HID;           pf.idx = SIDX + t * BATCH;
        pf.W = f_whh;                  pf.X = XF;
        pf.Cprev = BC;
        pf.Hout = HC + (long)t * (2 * HID) + HID;
        pf.Cout = BC + (long)t * HID;

        step_k<<<dim3(HID/64, BATCH/32, reset ? 1 : 2), 256>>>(pa, pf);
        if (reset)
            sib_reset<<<(BATCH * HID + 255) / 256, 256>>>(f_bih, f_bhh, t);
    }

    // OUT = tanh(HCAT @ pred_w^T + pred_b)     [5120, 512], K=1024
    {
        GemmP p{}; p.A = HC; p.lda = 2 * HID; p.B = pred_w; p.ldb = 2 * HID;
        p.C = OB; p.ldc = HID; p.bias1 = pred_b; p.act = 1;
        p.M = MTOT; p.N = HID; p.K = 2 * HID;
        gemm_k<128,128,32,4,2><<<dim3(HID/128, MTOT/128, 1), 256>>>(p, p);
    }
    // d_out = OUT @ logit_w^T + logit_b        [5120, 10000], K=512
    {
        GemmP p{}; p.A = OB; p.lda = HID; p.B = logit_w; p.ldb = HID;
        p.C = out; p.ldc = VOC; p.bias1 = logit_b;
        p.M = MTOT; p.N = VOC; p.K = HID;
        gemm_k<128,128,32,4,2><<<dim3((VOC + 127) / 128, MTOT/128, 1), 256>>>(p, p);
    }
    logsoftmax_k<<<MTOT, 256>>>(out);
}

// round 7
// speedup vs baseline: 1.2889x; 1.2889x over previous
#include <cuda_runtime.h>
#include <cuda_bf16.h>
#include <math.h>
#include <stdint.h>

#define BATCH 128
#define SEQ   40
#define HID   512
#define EMB   512
#define VOC   10000
#define FCF   2048
#define GATE4 2048            // 4*HID
#define MTOT  (BATCH*SEQ)     // 5120

// ---------------- workspaces (static device globals; no allocation) --------
__device__ float g_XA[MTOT*GATE4];
__device__ float g_XF[MTOT*GATE4];
__device__ float g_X0[BATCH*EMB];
__device__ float g_GATES[BATCH*2*GATE4];
__device__ float g_HCAT[MTOT*2*HID];
__device__ float g_CS[MTOT*HID];
__device__ float g_BC[MTOT*HID];
__device__ float g_OUT[MTOT*HID];
__device__ int   g_FIDX[MTOT];
__device__ int   g_SIDX[MTOT];
__device__ int   g_WIDX[MTOT];
__device__ int   g_IS64;

// ---------------- helpers ---------------------------------------------------
__device__ __forceinline__ unsigned pk2(float a, float b) {
    __nv_bfloat162 t = __floats2bfloat162_rn(a, b);   // .x = a (low half)
    return *reinterpret_cast<unsigned*>(&t);
}

__device__ __forceinline__ void mma_bf16(float* c, const unsigned* a, const unsigned* b) {
    asm volatile(
        "mma.sync.aligned.m16n8k16.row.col.f32.bf16.bf16.f32 "
        "{%0,%1,%2,%3}, {%4,%5,%6,%7}, {%8,%9}, {%0,%1,%2,%3};"
        : "+f"(c[0]), "+f"(c[1]), "+f"(c[2]), "+f"(c[3])
        : "r"(a[0]), "r"(a[1]), "r"(a[2]), "r"(a[3]), "r"(b[0]), "r"(b[1]));
}

__device__ __forceinline__ void ldsm4(unsigned* r, uint32_t addr) {
    asm volatile("ldmatrix.sync.aligned.m8n8.x4.shared.b16 {%0,%1,%2,%3}, [%4];"
        : "=r"(r[0]), "=r"(r[1]), "=r"(r[2]), "=r"(r[3]) : "r"(addr));
}

__device__ __forceinline__ uint32_t s2u(const void* p) {
    return (uint32_t)__cvta_generic_to_shared(p);
}

__device__ __forceinline__ float sigm(float x) { return 1.f / (1.f + expf(-x)); }

// ---------------- generic bf16 GEMM:  C = act(Agather @ B^T + Cadd + bias) --
struct GemmP {
    const float* A;    int lda;   const int* aidx;
    const float* B;    int ldb;
    const float* Cadd; int ldcadd;
    float*       C;    int ldc;
    const float* bias1; const float* bias2;
    int M, N, K;
    int act;  // 0 = none, 1 = tanh
};

__device__ __forceinline__ void gstore(const GemmP& p, int m, int n, float v) {
    if (m < p.M && n < p.N) {
        if (p.Cadd) {
            int cr = p.aidx ? p.aidx[m] : m;
            v += p.Cadd[(long)cr * p.ldcadd + n];
        }
        if (p.bias1) v += p.bias1[n];
        if (p.bias2) v += p.bias2[n];
        if (p.act) v = tanhf(v);
        p.C[(long)m * p.ldc + n] = v;
    }
}

// BK in ELEMENTS (multiple of 16). smem holds packed bf16x2 (k-pairs).
// NT must be even (B ldmatrix loads n-tile pairs).
template<int BM, int BN, int BK, int WRM, int WRN>
__global__ void __launch_bounds__(WRM*WRN*32)
gemm_k(GemmP P0, GemmP P1) {
    const GemmP p = (blockIdx.z == 0) ? P0 : P1;
    constexpr int THREADS = WRM * WRN * 32;
    constexpr int BKU = BK / 2;              // uints per row
    constexpr int BKP = BKU + 4;             // padded stride (16B-aligned rows)
    constexpr int WM = BM / WRM, WN = BN / WRN;
    constexpr int MT = WM / 16, NT = WN / 8;
    static_assert(NT % 2 == 0, "NT even");

    __shared__ unsigned sA[BM][BKP];
    __shared__ unsigned sB[BN][BKP];

    const int tid  = threadIdx.x;
    const int warp = tid >> 5, lane = tid & 31;
    const int g = lane >> 2, tig = lane & 3;
    const int wm = warp % WRM, wn = warp / WRM;
    const int bm0 = blockIdx.y * BM, bn0 = blockIdx.x * BN;

    const uint32_t sAu = s2u(&sA[0][0]);
    const uint32_t sBu = s2u(&sB[0][0]);
    // ldmatrix lane decomposition
    const int l8  = lane & 7;
    const int lh8 = (lane >> 3) & 1;   // row+8 selector (A) / k-half (B)
    const int lh16 = lane >> 4;        // k-half (A) / row+8 (B)

    float acc[MT][NT][4];
    #pragma unroll
    for (int mt = 0; mt < MT; mt++)
        #pragma unroll
        for (int nt = 0; nt < NT; nt++)
            #pragma unroll
            for (int q = 0; q < 4; q++) acc[mt][nt][q] = 0.f;

    constexpr int TPR = BK / 4;              // threads per row (float4)
    constexpr int RPI = THREADS / TPR;       // rows per iteration
    const int lr = tid / TPR;
    const int uc = (tid % TPR) * 2;          // uint col

    for (int k0 = 0; k0 < p.K; k0 += BK) {
        for (int r = lr; r < BM; r += RPI) {
            int m = bm0 + r;
            float4 v = make_float4(0.f, 0.f, 0.f, 0.f);
            if (m < p.M) {
                int row = p.aidx ? p.aidx[m] : m;
                v = *(const float4*)(p.A + (long)row * p.lda + k0 + uc * 2);
            }
            sA[r][uc    ] = pk2(v.x, v.y);
            sA[r][uc + 1] = pk2(v.z, v.w);
        }
        for (int r = lr; r < BN; r += RPI) {
            int n = bn0 + r;
            float4 v = make_float4(0.f, 0.f, 0.f, 0.f);
            if (n < p.N)
                v = *(const float4*)(p.B + (long)n * p.ldb + k0 + uc * 2);
            sB[r][uc    ] = pk2(v.x, v.y);
            sB[r][uc + 1] = pk2(v.z, v.w);
        }
        __syncthreads();

        #pragma unroll
        for (int ku = 0; ku < BKU; ku += 8) {      // one K=16 mma per step
            unsigned afr[MT][4];
            unsigned bfr[NT][2];
            #pragma unroll
            for (int mt = 0; mt < MT; mt++) {
                int mb = wm * WM + mt * 16;
                uint32_t a = sAu + (uint32_t)(((mb + lh8 * 8 + l8) * BKP) + ku + lh16 * 4) * 4u;
                ldsm4(afr[mt], a);
            }
            #pragma unroll
            for (int nt = 0; nt < NT; nt += 2) {
                int nb = wn * WN + nt * 8;
                uint32_t a = sBu + (uint32_t)(((nb + lh16 * 8 + l8) * BKP) + ku + lh8 * 4) * 4u;
                unsigned r[4]; ldsm4(r, a);
                bfr[nt][0]     = r[0]; bfr[nt][1]     = r[1];
                bfr[nt + 1][0] = r[2]; bfr[nt + 1][1] = r[3];
            }
            #pragma unroll
            for (int mt = 0; mt < MT; mt++)
                #pragma unroll
                for (int nt = 0; nt < NT; nt++)
                    mma_bf16(acc[mt][nt], afr[mt], bfr[nt]);
        }
        __syncthreads();
    }

    #pragma unroll
    for (int mt = 0; mt < MT; mt++) {
        int r0 = bm0 + wm * WM + mt * 16 + g;
        #pragma unroll
        for (int nt = 0; nt < NT; nt++) {
            int c0 = bn0 + wn * WN + nt * 8 + 2 * tig;
            gstore(p, r0,     c0,     acc[mt][nt][0]);
            gstore(p, r0,     c0 + 1, acc[mt][nt][1]);
            gstore(p, r0 + 8, c0,     acc[mt][nt][2]);
            gstore(p, r0 + 8, c0 + 1, acc[mt][nt][3]);
        }
    }
}

// ---------------- fused recurrent step kernel (bf16 MMA + ldmatrix) ---------
struct StepP {
    const float* Abase;
    const int*   idx;
    const float* W;       // whh [2048, 512] gate-major
    const float* X;       // XA/XF; biases folded in
    const float* Cprev;
    float*       Hout;
    float*       Cout;
};

__global__ void __launch_bounds__(256) step_k(StepP Pa, StepP Pf) {
    const StepP p = blockIdx.z ? Pf : Pa;
    const int u0 = blockIdx.x * 64;
    const int b0 = blockIdx.y * 32;

    // BK = 64 elements = 32 uints, stride 36
    __shared__ unsigned smem[32*36 + 256*36];
    unsigned (*sA)[36] = (unsigned(*)[36])smem;
    unsigned (*sB)[36] = (unsigned(*)[36])(smem + 32*36);
    float (*sG)[260] = (float(*)[260])smem;
    __shared__ int sIdx[32];

    const int tid  = threadIdx.x;
    const int warp = tid >> 5, lane = tid & 31;
    const int g = lane >> 2, tig = lane & 3;
    const int wm = warp & 1, wn = warp >> 1;    // 2x4 warps; WM=16, WN=64

    const uint32_t sAu = s2u(&sA[0][0]);
    const uint32_t sBu = s2u(&sB[0][0]);
    const int l8  = lane & 7;
    const int lh8 = (lane >> 3) & 1;
    const int lh16 = lane >> 4;

    if (tid < 32) sIdx[tid] = p.idx[b0 + tid];
    __syncthreads();

    float acc[8][4];
    #pragma unroll
    for (int nt = 0; nt < 8; nt++)
        #pragma unroll
        for (int q = 0; q < 4; q++) acc[nt][q] = 0.f;

    const int lr = tid >> 4;                 // 0..15
    const int uc = (tid & 15) * 2;

    for (int k0 = 0; k0 < 512; k0 += 64) {
        #pragma unroll
        for (int r = lr; r < 32; r += 16) {
            float4 v = *(const float4*)(p.Abase + (long)sIdx[r] * (2*HID) + k0 + uc * 2);
            sA[r][uc    ] = pk2(v.x, v.y);
            sA[r][uc + 1] = pk2(v.z, v.w);
        }
        #pragma unroll
        for (int r = lr; r < 256; r += 16) {
            int wrow = (r >> 6) * HID + u0 + (r & 63);
            float4 v = *(const float4*)(p.W + (long)wrow * HID + k0 + uc * 2);
            sB[r][uc    ] = pk2(v.x, v.y);
            sB[r][uc + 1] = pk2(v.z, v.w);
        }
        __syncthreads();

        #pragma unroll
        for (int ku = 0; ku < 32; ku += 8) {
            unsigned afr[4];
            {
                int mb = wm * 16;
                uint32_t a = sAu + (uint32_t)(((mb + lh8 * 8 + l8) * 36) + ku + lh16 * 4) * 4u;
                ldsm4(afr, a);
            }
            unsigned bfr[8][2];
            #pragma unroll
            for (int nt = 0; nt < 8; nt += 2) {
                int nb = wn * 64 + nt * 8;
                uint32_t a = sBu + (uint32_t)(((nb + lh16 * 8 + l8) * 36) + ku + lh8 * 4) * 4u;
                unsigned r[4]; ldsm4(r, a);
                bfr[nt][0]     = r[0]; bfr[nt][1]     = r[1];
                bfr[nt + 1][0] = r[2]; bfr[nt + 1][1] = r[3];
            }
            #pragma unroll
            for (int nt = 0; nt < 8; nt++)
                mma_bf16(acc[nt], afr, bfr[nt]);
        }
        __syncthreads();
    }

    // stage gates to shared (overwrites sA/sB region)
    #pragma unroll
    for (int nt = 0; nt < 8; nt++) {
        const int m = wm * 16 + g;
        const int n = wn * 64 + nt * 8 + 2 * tig;
        sG[m    ][n    ] = acc[nt][0];
        sG[m    ][n + 1] = acc[nt][1];
        sG[m + 8][n    ] = acc[nt][2];
        sG[m + 8][n + 1] = acc[nt][3];
    }
    __syncthreads();

    // cell math: 2048 elements / 256 threads = 8 each
    #pragma unroll
    for (int e = tid; e < 2048; e += 256) {
        const int m = e >> 6, ul = e & 63;
        const int b = b0 + m, u = u0 + ul;
        const long xr = sIdx[m];
        const float* xp = p.X + xr * (long)GATE4;
        float gi = sG[m][ul      ] + xp[u            ];
        float gf = sG[m][64 + ul ] + xp[HID + u      ];
        float gg = sG[m][128 + ul] + xp[2 * HID + u  ];
        float go = sG[m][192 + ul] + xp[3 * HID + u  ];
        float cp = p.Cprev[xr * HID + u];
        float c2 = sigm(gf) * cp + sigm(gi) * tanhf(gg);
        float h  = sigm(go) * tanhf(c2);
        p.Hout[(long)b * (SEQ * 2 * HID) + u] = h;
        p.Cout[(long)b * (SEQ * HID) + u]     = c2;
    }
}

// ---------------- sibling reset (bias-only f-cell) --------------------------
__global__ void sib_reset(const float* fb1, const float* fb2, int t) {
    int i = blockIdx.x * blockDim.x + threadIdx.x;
    if (i >= BATCH * HID) return;
    int b = i >> 9, u = i & (HID - 1);
    float fi = fb1[u]           + fb2[u];
    float fg = fb1[2*HID + u]   + fb2[2*HID + u];
    float fo = fb1[3*HID + u]   + fb2[3*HID + u];
    float bc2 = sigm(fi) * tanhf(fg);       // cprev = 0
    float bh  = sigm(fo) * tanhf(bc2);
    long orow = (long)b * SEQ + t;
    g_HCAT[orow * (2 * HID) + HID + u] = bh;
    g_BC[orow * HID + u] = bc2;
}

// ---------------- index dtype sniff + normalization -------------------------
__global__ void sniff_idx(const int* word32) {
    if (threadIdx.x == 0) {
        int allzero = 1;
        for (int i = 0; i < 64; i++)
            if (word32[2 * i + 1] != 0) { allzero = 0; break; }
        g_IS64 = allzero;
    }
}

__global__ void prep_idx(const int* word32, const int* father32) {
    int i = blockIdx.x * blockDim.x + threadIdx.x;
    if (i >= MTOT) return;
    int is64 = g_IS64;
    int w = is64 ? word32[2 * i]   : word32[i];
    int f = is64 ? father32[2 * i] : father32[i];
    g_WIDX[i] = w;
    int t = i % SEQ, b = i / SEQ;
    g_FIDX[t * BATCH + b] = b * SEQ + f;
    g_SIDX[t * BATCH + b] = b * SEQ + (t > 0 ? t - 1 : 0);
}

// ---------------- step-0 LSTM elementwise (generic path) --------------------
__global__ void lstm_ew0(const float* fb1, const float* fb2) {
    int i = blockIdx.x * blockDim.x + threadIdx.x;
    if (i >= BATCH * HID) return;
    int b = i >> 9, u = i & (HID - 1);
    const float* ga = g_GATES + (long)b * (2 * GATE4);
    float gi = ga[u], gg = ga[2*HID + u], go = ga[3*HID + u];
    float c2 = sigm(gi) * tanhf(gg);        // cprev = 0
    float ch = sigm(go) * tanhf(c2);
    long orow = (long)b * SEQ;      // t = 0
    g_HCAT[orow * (2 * HID) + u] = ch;
    g_CS[orow * HID + u] = c2;
    float fi = fb1[u]         + fb2[u];
    float fg = fb1[2*HID + u] + fb2[2*HID + u];
    float fo = fb1[3*HID + u] + fb2[3*HID + u];
    float bc2 = sigm(fi) * tanhf(fg);
    float bh  = sigm(fo) * tanhf(bc2);
    g_HCAT[orow * (2 * HID) + HID + u] = bh;
    g_BC[orow * HID + u] = bc2;
}

// ---------------- in-place log_softmax over rows of 10000 -------------------
__global__ void logsoftmax_k(float* out) {
    const long row = blockIdx.x;
    float* p = out + row * (long)VOC;
    const int tid = threadIdx.x;
    __shared__ float sred[8];

    float v[40];
    float mx = -INFINITY;
    #pragma unroll
    for (int j = 0; j < 40; j++) {
        int idx = j * 256 + tid;
        v[j] = (idx < VOC) ? p[idx] : -INFINITY;
        mx = fmaxf(mx, v[j]);
    }
    #pragma unroll
    for (int o = 16; o > 0; o >>= 1)
        mx = fmaxf(mx, __shfl_xor_sync(0xffffffffu, mx, o));
    if ((tid & 31) == 0) sred[tid >> 5] = mx;
    __syncthreads();
    float mall = -INFINITY;
    #pragma unroll
    for (int w = 0; w < 8; w++) mall = fmaxf(mall, sred[w]);
    __syncthreads();

    float s = 0.f;
    #pragma unroll
    for (int j = 0; j < 40; j++) {
        int idx = j * 256 + tid;
        if (idx < VOC) s += expf(v[j] - mall);
    }
    #pragma unroll
    for (int o = 16; o > 0; o >>= 1)
        s += __shfl_xor_sync(0xffffffffu, s, o);
    if ((tid & 31) == 0) sred[tid >> 5] = s;
    __syncthreads();
    float stot = 0.f;
    #pragma unroll
    for (int w = 0; w < 8; w++) stot += sred[w];

    float lse = mall + logf(stot);
    #pragma unroll
    for (int j = 0; j < 40; j++) {
        int idx = j * 256 + tid;
        if (idx < VOC) p[idx] = v[j] - lse;
    }
}

// ---------------- host orchestration ---------------------------------------
extern "C" void kernel_launch(void* const* d_in, const int* in_sizes, int n_in,
                              void* d_out, int out_size) {
    const int*   word    = (const int*)  d_in[0];
    const int*   father  = (const int*)  d_in[1];
    const float* fc_feats= (const float*)d_in[2];
    const float* embed   = (const float*)d_in[3];
    const float* fc_w    = (const float*)d_in[4];
    const float* fc_b    = (const float*)d_in[5];
    const float* a_wih   = (const float*)d_in[6];
    const float* a_whh   = (const float*)d_in[7];
    const float* a_bih   = (const float*)d_in[8];
    const float* a_bhh   = (const float*)d_in[9];
    const float* f_wih   = (const float*)d_in[10];
    const float* f_whh   = (const float*)d_in[11];
    const float* f_bih   = (const float*)d_in[12];
    const float* f_bhh   = (const float*)d_in[13];
    const float* pred_w  = (const float*)d_in[14];
    const float* pred_b  = (const float*)d_in[15];
    const float* logit_w = (const float*)d_in[16];
    const float* logit_b = (const float*)d_in[17];
    float* out = (float*)d_out;

    float *XA, *XF, *X0, *GT, *HC, *CS, *BC, *OB;
    int *FIDX, *SIDX, *WIDX;
    cudaGetSymbolAddress((void**)&XA,  g_XA);
    cudaGetSymbolAddress((void**)&XF,  g_XF);
    cudaGetSymbolAddress((void**)&X0,  g_X0);
    cudaGetSymbolAddress((void**)&GT,  g_GATES);
    cudaGetSymbolAddress((void**)&HC,  g_HCAT);
    cudaGetSymbolAddress((void**)&CS,  g_CS);
    cudaGetSymbolAddress((void**)&BC,  g_BC);
    cudaGetSymbolAddress((void**)&OB,  g_OUT);
    cudaGetSymbolAddress((void**)&FIDX, g_FIDX);
    cudaGetSymbolAddress((void**)&SIDX, g_SIDX);
    cudaGetSymbolAddress((void**)&WIDX, g_WIDX);

    sniff_idx<<<1, 32>>>(word);
    prep_idx<<<(MTOT + 255) / 256, 256>>>(word, father);

    // X0 = fc_feats @ fc_w^T + fc_b            [128, 512], K=2048
    {
        GemmP p{}; p.A = fc_feats; p.lda = FCF; p.B = fc_w; p.ldb = FCF;
        p.C = X0; p.ldc = EMB; p.bias1 = fc_b;
        p.M = BATCH; p.N = EMB; p.K = FCF;
        gemm_k<32,64,64,1,2><<<dim3(EMB/64, BATCH/32, 1), 64>>>(p, p);
    }
    // XA/XF = embed[word] @ {a,f}_wih^T + biases   [5120, 2048], K=512 (z=2)
    {
        GemmP pa{}; pa.A = embed; pa.lda = EMB; pa.aidx = WIDX;
        pa.B = a_wih; pa.ldb = EMB; pa.C = XA; pa.ldc = GATE4;
        pa.bias1 = a_bih; pa.bias2 = a_bhh;
        pa.M = MTOT; pa.N = GATE4; pa.K = EMB;
        GemmP pf = pa;
        pf.B = f_wih; pf.C = XF; pf.bias1 = f_bih; pf.bias2 = f_bhh;
        gemm_k<128,128,64,4,2><<<dim3(GATE4/128, MTOT/128, 2), 256>>>(pa, pf);
    }
    // step 0 a-gates: GT = X0 @ a_wih^T + a_bih + a_bhh
    {
        GemmP p{}; p.A = X0; p.lda = EMB; p.B = a_wih; p.ldb = EMB;
        p.C = GT; p.ldc = 2 * GATE4; p.bias1 = a_bih; p.bias2 = a_bhh;
        p.M = BATCH; p.N = GATE4; p.K = EMB;
        gemm_k<32,64,64,1,2><<<dim3(GATE4/64, BATCH/32, 1), 64>>>(p, p);
    }
    lstm_ew0<<<(BATCH * HID + 255) / 256, 256>>>(f_bih, f_bhh);

    // recurrent steps (fused GEMM + cell)
    for (int t = 1; t < SEQ; t++) {
        int reset = ((t - 1) % 3 == 0) ? 1 : 0;

        StepP pa{};
        pa.Abase = HC;                 pa.idx = FIDX + t * BATCH;
        pa.W = a_whh;                  pa.X = XA;
        pa.Cprev = CS;
        pa.Hout = HC + (long)t * (2 * HID);
        pa.Cout = CS + (long)t * HID;

        StepP pf{};
        pf.Abase = HC + HID;           pf.idx = SIDX + t * BATCH;
        pf.W = f_whh;                  pf.X = XF;
        pf.Cprev = BC;
        pf.Hout = HC + (long)t * (2 * HID) + HID;
        pf.Cout = BC + (long)t * HID;

        step_k<<<dim3(HID/64, BATCH/32, reset ? 1 : 2), 256>>>(pa, pf);
        if (reset)
            sib_reset<<<(BATCH * HID + 255) / 256, 256>>>(f_bih, f_bhh, t);
    }

    // OUT = tanh(HCAT @ pred_w^T + pred_b)     [5120, 512], K=1024
    {
        GemmP p{}; p.A = HC; p.lda = 2 * HID; p.B = pred_w; p.ldb = 2 * HID;
        p.C = OB; p.ldc = HID; p.bias1 = pred_b; p.act = 1;
        p.M = MTOT; p.N = HID; p.K = 2 * HID;
        gemm_k<128,128,64,4,2><<<dim3(HID/128, MTOT/128, 1), 256>>>(p, p);
    }
    // d_out = OUT @ logit_w^T + logit_b        [5120, 10000], K=512
    {
        GemmP p{}; p.A = OB; p.lda = HID; p.B = logit_w; p.ldb = HID;
        p.C = out; p.ldc = VOC; p.bias1 = logit_b;
        p.M = MTOT; p.N = VOC; p.K = HID;
        gemm_k<128,128,64,4,2><<<dim3((VOC + 127) / 128, MTOT/128, 1), 256>>>(p, p);
    }
    logsoftmax_k<<<MTOT, 256>>>(out);
}

// round 11
// speedup vs baseline: 2.5700x; 1.9940x over previous
#include <cuda_runtime.h>
#include <cuda_bf16.h>
#include <math.h>
#include <stdint.h>

#define BATCH 128
#define SEQ   40
#define HID   512
#define EMB   512
#define VOC   10000
#define FCF   2048
#define GATE4 2048            // 4*HID
#define MTOT  (BATCH*SEQ)     // 5120

typedef __nv_bfloat16 bf16;

// ---------------- f32 workspaces -------------------------------------------
__device__ float g_XA[MTOT*GATE4];
__device__ float g_XF[MTOT*GATE4];
__device__ float g_GATES[BATCH*2*GATE4];
__device__ float g_CS[MTOT*HID];
__device__ float g_BC[MTOT*HID];
__device__ int   g_FIDX[MTOT];
__device__ int   g_SIDX[MTOT];
__device__ int   g_WIDX[MTOT];
__device__ int   g_IS64;

// ---------------- bf16 operand workspaces ----------------------------------
__device__ bf16 g_EMBB [VOC*EMB];
__device__ bf16 g_AWIH [GATE4*EMB];
__device__ bf16 g_FWIH [GATE4*EMB];
__device__ bf16 g_AWHH [GATE4*HID];
__device__ bf16 g_FWHH [GATE4*HID];
__device__ bf16 g_PREDW[HID*2*HID];
__device__ bf16 g_LOGW [VOC*HID];
__device__ bf16 g_FCW  [EMB*FCF];
__device__ bf16 g_FCFB [BATCH*FCF];
__device__ bf16 g_X0B  [BATCH*EMB];
__device__ bf16 g_HCATB[MTOT*2*HID];   // [b*SEQ+t][ch | bh]
__device__ bf16 g_OUTB [MTOT*HID];

// ---------------- helpers ---------------------------------------------------
__device__ __forceinline__ unsigned pk2(float a, float b) {
    __nv_bfloat162 t = __floats2bfloat162_rn(a, b);
    return *reinterpret_cast<unsigned*>(&t);
}

__device__ __forceinline__ void mma_bf16(float* c, const unsigned* a, const unsigned* b) {
    asm volatile(
        "mma.sync.aligned.m16n8k16.row.col.f32.bf16.bf16.f32 "
        "{%0,%1,%2,%3}, {%4,%5,%6,%7}, {%8,%9}, {%0,%1,%2,%3};"
        : "+f"(c[0]), "+f"(c[1]), "+f"(c[2]), "+f"(c[3])
        : "r"(a[0]), "r"(a[1]), "r"(a[2]), "r"(a[3]), "r"(b[0]), "r"(b[1]));
}

__device__ __forceinline__ void ldsm4(unsigned* r, uint32_t addr) {
    asm volatile("ldmatrix.sync.aligned.m8n8.x4.shared.b16 {%0,%1,%2,%3}, [%4];"
        : "=r"(r[0]), "=r"(r[1]), "=r"(r[2]), "=r"(r[3]) : "r"(addr));
}

__device__ __forceinline__ uint32_t s2u(const void* p) {
    return (uint32_t)__cvta_generic_to_shared(p);
}

__device__ __forceinline__ void cpa16(uint32_t dst, const void* src, bool pred) {
    asm volatile("cp.async.ca.shared.global [%0], [%1], 16, %2;"
        :: "r"(dst), "l"(src), "r"(pred ? 16 : 0));
}
#define CP_COMMIT asm volatile("cp.async.commit_group;")
template<int N> __device__ __forceinline__ void cp_wait() {
    asm volatile("cp.async.wait_group %0;" :: "n"(N));
}

__device__ __forceinline__ float sigm(float x) { return 1.f / (1.f + expf(-x)); }

// ---------------- f32 -> bf16 conversion ------------------------------------
__global__ void f2b(const float* s, bf16* d, int n) {
    int i = (blockIdx.x * blockDim.x + threadIdx.x) * 4;
    if (i < n) {
        float4 v = *(const float4*)(s + i);
        unsigned* du = (unsigned*)(d + i);
        du[0] = pk2(v.x, v.y);
        du[1] = pk2(v.z, v.w);
    }
}

// ---------------- bf16 GEMM, cp.async 2-stage pipeline ----------------------
// C = act(Agather @ B^T + bias); A,B bf16; out f32 (C) and/or bf16 (Cb).
struct GemmB {
    const bf16* A;  int lda;  const int* aidx;
    const bf16* B;  int ldb;
    float*      C;  int ldc;
    bf16*       Cb; int ldcb;
    const float* bias1; const float* bias2;
    int M, N, K;
    int act;
};

__device__ __forceinline__ void gstoreB(const GemmB& p, int m, int n, float v) {
    if (m < p.M && n < p.N) {
        if (p.bias1) v += p.bias1[n];
        if (p.bias2) v += p.bias2[n];
        if (p.act) v = tanhf(v);
        if (p.C)  p.C [(long)m * p.ldc  + n] = v;
        if (p.Cb) p.Cb[(long)m * p.ldcb + n] = __float2bfloat16(v);
    }
}

// BK = 32 elements (64B/row), BKU=16 uints, BKP=20 (16B-aligned stride).
template<int BM, int BN, int WRM, int WRN>
__global__ void __launch_bounds__(WRM*WRN*32)
gemm_k(GemmB P0, GemmB P1) {
    const GemmB p = (blockIdx.z == 0) ? P0 : P1;
    constexpr int THREADS = WRM * WRN * 32;
    constexpr int BKP = 20;
    constexpr int WM = BM / WRM, WN = BN / WRN;
    constexpr int MT = WM / 16, NT = WN / 8;
    static_assert(NT % 2 == 0, "NT even");

    __shared__ unsigned smem[2*BM*BKP + 2*BN*BKP];
    __shared__ int sIdxA[BM];

    const int tid  = threadIdx.x;
    const int warp = tid >> 5, lane = tid & 31;
    const int g = lane >> 2, tig = lane & 3;
    const int wm = warp % WRM, wn = warp / WRM;
    const int bm0 = blockIdx.y * BM, bn0 = blockIdx.x * BN;

    const uint32_t su = s2u(smem);
    const int l8  = lane & 7;
    const int lh8 = (lane >> 3) & 1;
    const int lh16 = lane >> 4;

    for (int r = tid; r < BM; r += THREADS) {
        int m = bm0 + r;
        sIdxA[r] = (m < p.M) ? (p.aidx ? p.aidx[m] : m) : 0;
    }
    __syncthreads();

    float acc[MT][NT][4];
    #pragma unroll
    for (int mt = 0; mt < MT; mt++)
        #pragma unroll
        for (int nt = 0; nt < NT; nt++)
            #pragma unroll
            for (int q = 0; q < 4; q++) acc[mt][nt][q] = 0.f;

    auto issue = [&](int st, int k0) {
        #pragma unroll 2
        for (int c = tid; c < BM * 4; c += THREADS) {
            int r = c >> 2, off = c & 3;
            uint32_t dst = su + (uint32_t)(st * BM * BKP + r * BKP + off * 4) * 4u;
            cpa16(dst, p.A + (long)sIdxA[r] * p.lda + k0 + off * 8, bm0 + r < p.M);
        }
        #pragma unroll 2
        for (int c = tid; c < BN * 4; c += THREADS) {
            int r = c >> 2, off = c & 3;
            int n = bn0 + r;
            bool ok = n < p.N;
            uint32_t dst = su + (uint32_t)(2*BM*BKP + st * BN * BKP + r * BKP + off * 4) * 4u;
            cpa16(dst, p.B + (long)(ok ? n : 0) * p.ldb + k0 + off * 8, ok);
        }
        CP_COMMIT;
    };

    const int KT = p.K >> 5;
    issue(0, 0);
    for (int kt = 0; kt < KT; kt++) {
        const int st = kt & 1;
        if (kt + 1 < KT) { issue(st ^ 1, (kt + 1) << 5); cp_wait<1>(); }
        else             { cp_wait<0>(); }
        __syncthreads();

        const uint32_t aBase = su + (uint32_t)(st * BM * BKP) * 4u;
        const uint32_t bBase = su + (uint32_t)(2*BM*BKP + st * BN * BKP) * 4u;
        #pragma unroll
        for (int ku = 0; ku < 16; ku += 8) {
            unsigned afr[MT][4];
            unsigned bfr[NT][2];
            #pragma unroll
            for (int mt = 0; mt < MT; mt++) {
                int mb = wm * WM + mt * 16;
                ldsm4(afr[mt], aBase + (uint32_t)((mb + lh8*8 + l8) * BKP + ku + lh16*4) * 4u);
            }
            #pragma unroll
            for (int nt = 0; nt < NT; nt += 2) {
                int nb = wn * WN + nt * 8;
                unsigned r[4];
                ldsm4(r, bBase + (uint32_t)((nb + lh16*8 + l8) * BKP + ku + lh8*4) * 4u);
                bfr[nt][0] = r[0]; bfr[nt][1] = r[1];
                bfr[nt+1][0] = r[2]; bfr[nt+1][1] = r[3];
            }
            #pragma unroll
            for (int mt = 0; mt < MT; mt++)
                #pragma unroll
                for (int nt = 0; nt < NT; nt++)
                    mma_bf16(acc[mt][nt], afr[mt], bfr[nt]);
        }
        __syncthreads();
    }

    #pragma unroll
    for (int mt = 0; mt < MT; mt++) {
        int r0 = bm0 + wm * WM + mt * 16 + g;
        #pragma unroll
        for (int nt = 0; nt < NT; nt++) {
            int c0 = bn0 + wn * WN + nt * 8 + 2 * tig;
            gstoreB(p, r0,     c0,     acc[mt][nt][0]);
            gstoreB(p, r0,     c0 + 1, acc[mt][nt][1]);
            gstoreB(p, r0 + 8, c0,     acc[mt][nt][2]);
            gstoreB(p, r0 + 8, c0 + 1, acc[mt][nt][3]);
        }
    }
}

// ---------------- fused recurrent step kernel (cp.async + bf16) -------------
struct StepP {
    const bf16*  Abase;   // HCATB (+HID for f); row = idx[m]*1024
    const int*   idx;
    const bf16*  W;       // whh bf16 [2048, 512] gate-major
    const float* X;       // XA/XF f32; biases folded in
    const float* Cprev;
    bf16*        Hout;    // HCATB + t*1024 (+HID for f)
    float*       Cout;
};

__global__ void __launch_bounds__(256) step_k(StepP Pa, StepP Pf) {
    const StepP p = blockIdx.z ? Pf : Pa;
    const int u0 = blockIdx.x * 64;
    const int b0 = blockIdx.y * 32;

    // 2 stages: A 32x20, B 256x20 uints
    __shared__ unsigned smem[2*32*20 + 2*256*20];   // 46080 B
    float (*sG)[260] = (float(*)[260])smem;
    __shared__ int sIdx[32];

    const int tid  = threadIdx.x;
    const int warp = tid >> 5, lane = tid & 31;
    const int g = lane >> 2, tig = lane & 3;
    const int wm = warp & 1, wn = warp >> 1;    // 2x4 warps; WM=16, WN=64

    const uint32_t su = s2u(smem);
    const int l8  = lane & 7;
    const int lh8 = (lane >> 3) & 1;
    const int lh16 = lane >> 4;

    if (tid < 32) sIdx[tid] = p.idx[b0 + tid];
    __syncthreads();

    float acc[8][4];
    #pragma unroll
    for (int nt = 0; nt < 8; nt++)
        #pragma unroll
        for (int q = 0; q < 4; q++) acc[nt][q] = 0.f;

    auto issue = [&](int st, int k0) {
        if (tid < 128) {               // A: 32 rows x 4 chunks
            int r = tid >> 2, off = tid & 3;
            uint32_t dst = su + (uint32_t)(st * 640 + r * 20 + off * 4) * 4u;
            cpa16(dst, p.Abase + (long)sIdx[r] * (2*HID) + k0 + off * 8, true);
        }
        #pragma unroll
        for (int c = tid; c < 1024; c += 256) {   // B: 256 rows x 4 chunks
            int r = c >> 2, off = c & 3;
            int wrow = (r >> 6) * HID + u0 + (r & 63);
            uint32_t dst = su + (uint32_t)(1280 + st * 5120 + r * 20 + off * 4) * 4u;
            cpa16(dst, p.W + (long)wrow * HID + k0 + off * 8, true);
        }
        CP_COMMIT;
    };

    issue(0, 0);
    #pragma unroll 1
    for (int kt = 0; kt < 16; kt++) {
        const int st = kt & 1;
        if (kt + 1 < 16) { issue(st ^ 1, (kt + 1) << 5); cp_wait<1>(); }
        else             { cp_wait<0>(); }
        __syncthreads();

        const uint32_t aBase = su + (uint32_t)(st * 640) * 4u;
        const uint32_t bBase = su + (uint32_t)(1280 + st * 5120) * 4u;
        #pragma unroll
        for (int ku = 0; ku < 16; ku += 8) {
            unsigned afr[4];
            {
                int mb = wm * 16;
                ldsm4(afr, aBase + (uint32_t)((mb + lh8*8 + l8) * 20 + ku + lh16*4) * 4u);
            }
            unsigned bfr[8][2];
            #pragma unroll
            for (int nt = 0; nt < 8; nt += 2) {
                int nb = wn * 64 + nt * 8;
                unsigned r[4];
                ldsm4(r, bBase + (uint32_t)((nb + lh16*8 + l8) * 20 + ku + lh8*4) * 4u);
                bfr[nt][0] = r[0]; bfr[nt][1] = r[1];
                bfr[nt+1][0] = r[2]; bfr[nt+1][1] = r[3];
            }
            #pragma unroll
            for (int nt = 0; nt < 8; nt++)
                mma_bf16(acc[nt], afr, bfr[nt]);
        }
        __syncthreads();
    }

    // stage gates to shared (overlays pipeline buffers)
    #pragma unroll
    for (int nt = 0; nt < 8; nt++) {
        const int m = wm * 16 + g;
        const int n = wn * 64 + nt * 8 + 2 * tig;
        sG[m    ][n    ] = acc[nt][0];
        sG[m    ][n + 1] = acc[nt][1];
        sG[m + 8][n    ] = acc[nt][2];
        sG[m + 8][n + 1] = acc[nt][3];
    }
    __syncthreads();

    #pragma unroll
    for (int e = tid; e < 2048; e += 256) {
        const int m = e >> 6, ul = e & 63;
        const int b = b0 + m, u = u0 + ul;
        const long xr = sIdx[m];
        const float* xp = p.X + xr * (long)GATE4;
        float gi = sG[m][ul      ] + xp[u            ];
        float gf = sG[m][64 + ul ] + xp[HID + u      ];
        float gg = sG[m][128 + ul] + xp[2 * HID + u  ];
        float go = sG[m][192 + ul] + xp[3 * HID + u  ];
        float cp = p.Cprev[xr * HID + u];
        float c2 = sigm(gf) * cp + sigm(gi) * tanhf(gg);
        float h  = sigm(go) * tanhf(c2);
        p.Hout[(long)b * (SEQ * 2 * HID) + u] = __float2bfloat16(h);
        p.Cout[(long)b * (SEQ * HID) + u]     = c2;
    }
}

// ---------------- sibling reset: t-invariant, all 13 reset slots at once ----
__global__ void sib_reset_all(const float* fb1, const float* fb2) {
    int i = blockIdx.x * blockDim.x + threadIdx.x;
    if (i >= BATCH * HID) return;
    int b = i >> 9, u = i & (HID - 1);
    float fi = fb1[u]         + fb2[u];
    float fg = fb1[2*HID + u] + fb2[2*HID + u];
    float fo = fb1[3*HID + u] + fb2[3*HID + u];
    float bc2 = sigm(fi) * tanhf(fg);       // cprev = 0
    bf16 bhb = __float2bfloat16(sigm(fo) * tanhf(bc2));
    #pragma unroll
    for (int t = 1; t < SEQ; t += 3) {      // (t-1)%3==0 -> t = 1,4,...,37
        long orow = (long)b * SEQ + t;
        g_HCATB[orow * (2 * HID) + HID + u] = bhb;
        g_BC[orow * HID + u] = bc2;
    }
}

// ---------------- index dtype sniff + normalization -------------------------
__global__ void sniff_idx(const int* word32) {
    if (threadIdx.x == 0) {
        int allzero = 1;
        for (int i = 0; i < 64; i++)
            if (word32[2 * i + 1] != 0) { allzero = 0; break; }
        g_IS64 = allzero;
    }
}

__global__ void prep_idx(const int* word32, const int* father32) {
    int i = blockIdx.x * blockDim.x + threadIdx.x;
    if (i >= MTOT) return;
    int is64 = g_IS64;
    int w = is64 ? word32[2 * i]   : word32[i];
    int f = is64 ? father32[2 * i] : father32[i];
    g_WIDX[i] = w;
    int t = i % SEQ, b = i / SEQ;
    g_FIDX[t * BATCH + b] = b * SEQ + f;
    g_SIDX[t * BATCH + b] = b * SEQ + (t > 0 ? t - 1 : 0);
}

// ---------------- step-0 LSTM elementwise -----------------------------------
__global__ void lstm_ew0(const float* fb1, const float* fb2) {
    int i = blockIdx.x * blockDim.x + threadIdx.x;
    if (i >= BATCH * HID) return;
    int b = i >> 9, u = i & (HID - 1);
    const float* ga = g_GATES + (long)b * (2 * GATE4);
    float gi = ga[u], gg = ga[2*HID + u], go = ga[3*HID + u];
    float c2 = sigm(gi) * tanhf(gg);
    float ch = sigm(go) * tanhf(c2);
    long orow = (long)b * SEQ;
    g_HCATB[orow * (2 * HID) + u] = __float2bfloat16(ch);
    g_CS[orow * HID + u] = c2;
    float fi = fb1[u]         + fb2[u];
    float fg = fb1[2*HID + u] + fb2[2*HID + u];
    float fo = fb1[3*HID + u] + fb2[3*HID + u];
    float bc2 = sigm(fi) * tanhf(fg);
    float bh  = sigm(fo) * tanhf(bc2);
    g_HCATB[orow * (2 * HID) + HID + u] = __float2bfloat16(bh);
    g_BC[orow * HID + u] = bc2;
}

// ---------------- in-place log_softmax over rows of 10000 -------------------
__global__ void logsoftmax_k(float* out) {
    const long row = blockIdx.x;
    float* p = out + row * (long)VOC;
    const int tid = threadIdx.x;
    __shared__ float sred[8];

    float v[40];
    float mx = -INFINITY;
    #pragma unroll
    for (int j = 0; j < 40; j++) {
        int idx = j * 256 + tid;
        v[j] = (idx < VOC) ? p[idx] : -INFINITY;
        mx = fmaxf(mx, v[j]);
    }
    #pragma unroll
    for (int o = 16; o > 0; o >>= 1)
        mx = fmaxf(mx, __shfl_xor_sync(0xffffffffu, mx, o));
    if ((tid & 31) == 0) sred[tid >> 5] = mx;
    __syncthreads();
    float mall = -INFINITY;
    #pragma unroll
    for (int w = 0; w < 8; w++) mall = fmaxf(mall, sred[w]);
    __syncthreads();

    float s = 0.f;
    #pragma unroll
    for (int j = 0; j < 40; j++) {
        int idx = j * 256 + tid;
        if (idx < VOC) s += expf(v[j] - mall);
    }
    #pragma unroll
    for (int o = 16; o > 0; o >>= 1)
        s += __shfl_xor_sync(0xffffffffu, s, o);
    if ((tid & 31) == 0) sred[tid >> 5] = s;
    __syncthreads();
    float stot = 0.f;
    #pragma unroll
    for (int w = 0; w < 8; w++) stot += sred[w];

    float lse = mall + logf(stot);
    #pragma unroll
    for (int j = 0; j < 40; j++) {
        int idx = j * 256 + tid;
        if (idx < VOC) p[idx] = v[j] - lse;
    }
}

// ---------------- host orchestration ---------------------------------------
extern "C" void kernel_launch(void* const* d_in, const int* in_sizes, int n_in,
                              void* d_out, int out_size) {
    const int*   word    = (const int*)  d_in[0];
    const int*   father  = (const int*)  d_in[1];
    const float* fc_feats= (const float*)d_in[2];
    const float* embed   = (const float*)d_in[3];
    const float* fc_w    = (const float*)d_in[4];
    const float* fc_b    = (const float*)d_in[5];
    const float* a_wih   = (const float*)d_in[6];
    const float* a_whh   = (const float*)d_in[7];
    const float* a_bih   = (const float*)d_in[8];
    const float* a_bhh   = (const float*)d_in[9];
    const float* f_wih   = (const float*)d_in[10];
    const float* f_whh   = (const float*)d_in[11];
    const float* f_bih   = (const float*)d_in[12];
    const float* f_bhh   = (const float*)d_in[13];
    const float* pred_w  = (const float*)d_in[14];
    const float* pred_b  = (const float*)d_in[15];
    const float* logit_w = (const float*)d_in[16];
    const float* logit_b = (const float*)d_in[17];
    float* out = (float*)d_out;

    float *XA, *XF, *GT, *CS, *BC;
    int *FIDX, *SIDX, *WIDX;
    bf16 *EMBB, *AWIH, *FWIH, *AWHH, *FWHH, *PREDW, *LOGW, *FCW, *FCFB, *X0B, *HCB, *OUTB;
    cudaGetSymbolAddress((void**)&XA,  g_XA);
    cudaGetSymbolAddress((void**)&XF,  g_XF);
    cudaGetSymbolAddress((void**)&GT,  g_GATES);
    cudaGetSymbolAddress((void**)&CS,  g_CS);
    cudaGetSymbolAddress((void**)&BC,  g_BC);
    cudaGetSymbolAddress((void**)&FIDX, g_FIDX);
    cudaGetSymbolAddress((void**)&SIDX, g_SIDX);
    cudaGetSymbolAddress((void**)&WIDX, g_WIDX);
    cudaGetSymbolAddress((void**)&EMBB, g_EMBB);
    cudaGetSymbolAddress((void**)&AWIH, g_AWIH);
    cudaGetSymbolAddress((void**)&FWIH, g_FWIH);
    cudaGetSymbolAddress((void**)&AWHH, g_AWHH);
    cudaGetSymbolAddress((void**)&FWHH, g_FWHH);
    cudaGetSymbolAddress((void**)&PREDW, g_PREDW);
    cudaGetSymbolAddress((void**)&LOGW, g_LOGW);
    cudaGetSymbolAddress((void**)&FCW,  g_FCW);
    cudaGetSymbolAddress((void**)&FCFB, g_FCFB);
    cudaGetSymbolAddress((void**)&X0B,  g_X0B);
    cudaGetSymbolAddress((void**)&HCB,  g_HCATB);
    cudaGetSymbolAddress((void**)&OUTB, g_OUTB);

    sniff_idx<<<1, 32>>>(word);
    prep_idx<<<(MTOT + 255) / 256, 256>>>(word, father);

    // one-time f32 -> bf16 conversions
    #define CVT(src, dst, n) f2b<<<((n)/4 + 255)/256, 256>>>(src, dst, n)
    CVT(embed,   EMBB,  VOC*EMB);
    CVT(a_wih,   AWIH,  GATE4*EMB);
    CVT(f_wih,   FWIH,  GATE4*EMB);
    CVT(a_whh,   AWHH,  GATE4*HID);
    CVT(f_whh,   FWHH,  GATE4*HID);
    CVT(pred_w,  PREDW, HID*2*HID);
    CVT(logit_w, LOGW,  VOC*HID);
    CVT(fc_w,    FCW,   EMB*FCF);
    CVT(fc_feats,FCFB,  BATCH*FCF);
    #undef CVT

    // X0B = bf16(fc_feats @ fc_w^T + fc_b)     [128, 512], K=2048
    {
        GemmB p{}; p.A = FCFB; p.lda = FCF; p.B = FCW; p.ldb = FCF;
        p.Cb = X0B; p.ldcb = EMB; p.bias1 = fc_b;
        p.M = BATCH; p.N = EMB; p.K = FCF;
        gemm_k<32,64,1,2><<<dim3(EMB/64, BATCH/32, 1), 64>>>(p, p);
    }
    // XA/XF = embed[word] @ {a,f}_wih^T + biases   [5120, 2048], K=512 (z=2)
    {
        GemmB pa{}; pa.A = EMBB; pa.lda = EMB; pa.aidx = WIDX;
        pa.B = AWIH; pa.ldb = EMB; pa.C = XA; pa.ldc = GATE4;
        pa.bias1 = a_bih; pa.bias2 = a_bhh;
        pa.M = MTOT; pa.N = GATE4; pa.K = EMB;
        GemmB pf = pa;
        pf.B = FWIH; pf.C = XF; pf.bias1 = f_bih; pf.bias2 = f_bhh;
        gemm_k<128,128,4,2><<<dim3(GATE4/128, MTOT/128, 2), 256>>>(pa, pf);
    }
    // step 0 a-gates: GT = X0 @ a_wih^T + a_bih + a_bhh
    {
        GemmB p{}; p.A = X0B; p.lda = EMB; p.B = AWIH; p.ldb = EMB;
        p.C = GT; p.ldc = 2 * GATE4; p.bias1 = a_bih; p.bias2 = a_bhh;
        p.M = BATCH; p.N = GATE4; p.K = EMB;
        gemm_k<32,64,1,2><<<dim3(GATE4/64, BATCH/32, 1), 64>>>(p, p);
    }
    lstm_ew0<<<(BATCH * HID + 255) / 256, 256>>>(f_bih, f_bhh);
    // pre-write ALL sibling-reset slots (t-invariant values; slots untouched
    // by step_k on reset steps, consumed only at t+1)
    sib_reset_all<<<(BATCH * HID + 255) / 256, 256>>>(f_bih, f_bhh);

    // recurrent steps (fused GEMM + cell)
    for (int t = 1; t < SEQ; t++) {
        int reset = ((t - 1) % 3 == 0) ? 1 : 0;

        StepP pa{};
        pa.Abase = HCB;                pa.idx = FIDX + t * BATCH;
        pa.W = AWHH;                   pa.X = XA;
        pa.Cprev = CS;
        pa.Hout = HCB + (long)t * (2 * HID);
        pa.Cout = CS + (long)t * HID;

        StepP pf{};
        pf.Abase = HCB + HID;          pf.idx = SIDX + t * BATCH;
        pf.W = FWHH;                   pf.X = XF;
        pf.Cprev = BC;
        pf.Hout = HCB + (long)t * (2 * HID) + HID;
        pf.Cout = BC + (long)t * HID;

        step_k<<<dim3(HID/64, BATCH/32, reset ? 1 : 2), 256>>>(pa, pf);
    }

    // OUTB = bf16(tanh(HCATB @ pred_w^T + pred_b))   [5120, 512], K=1024
    {
        GemmB p{}; p.A = HCB; p.lda = 2 * HID; p.B = PREDW; p.ldb = 2 * HID;
        p.Cb = OUTB; p.ldcb = HID; p.bias1 = pred_b; p.act = 1;
        p.M = MTOT; p.N = HID; p.K = 2 * HID;
        gemm_k<128,128,4,2><<<dim3(HID/128, MTOT/128, 1), 256>>>(p, p);
    }
    // d_out = OUTB @ logit_w^T + logit_b        [5120, 10000], K=512
    {
        GemmB p{}; p.A = OUTB; p.lda = HID; p.B = LOGW; p.ldb = HID;
        p.C = out; p.ldc = VOC; p.bias1 = logit_b;
        p.M = MTOT; p.N = VOC; p.K = HID;
        gemm_k<128,128,4,2><<<dim3((VOC + 127) / 128, MTOT/128, 1), 256>>>(p, p);
    }
    logsoftmax_k<<<MTOT, 256>>>(out);
}

// round 14
// speedup vs baseline: 2.6541x; 1.0327x over previous
#include <cuda_runtime.h>
#include <cuda_bf16.h>
#include <math.h>
#include <stdint.h>

#define BATCH 128
#define SEQ   40
#define HID   512
#define EMB   512
#define VOC   10000
#define FCF   2048
#define GATE4 2048            // 4*HID
#define MTOT  (BATCH*SEQ)     // 5120

typedef __nv_bfloat16 bf16;

// ---------------- f32 workspaces -------------------------------------------
__device__ float g_XA[MTOT*GATE4];
__device__ float g_XF[MTOT*GATE4];
__device__ float g_GATES[BATCH*2*GATE4];
__device__ float g_CS[MTOT*HID];
__device__ float g_BC[MTOT*HID];
__device__ int   g_FIDX[MTOT];
__device__ int   g_SIDX[MTOT];
__device__ int   g_WIDX[MTOT];
__device__ int   g_IS64;
__device__ unsigned g_bar;             // persistent-kernel barrier counter

// ---------------- bf16 operand workspaces ----------------------------------
__device__ bf16 g_EMBB [VOC*EMB];
__device__ bf16 g_AWIH [GATE4*EMB];
__device__ bf16 g_FWIH [GATE4*EMB];
__device__ bf16 g_AWHH [GATE4*HID];
__device__ bf16 g_FWHH [GATE4*HID];
__device__ bf16 g_PREDW[HID*2*HID];
__device__ bf16 g_LOGW [VOC*HID];
__device__ bf16 g_FCW  [EMB*FCF];
__device__ bf16 g_FCFB [BATCH*FCF];
__device__ bf16 g_X0B  [BATCH*EMB];
__device__ bf16 g_HCATB[MTOT*2*HID];   // [b*SEQ+t][ch | bh]
__device__ bf16 g_OUTB [MTOT*HID];

// ---------------- helpers ---------------------------------------------------
__device__ __forceinline__ unsigned pk2(float a, float b) {
    __nv_bfloat162 t = __floats2bfloat162_rn(a, b);
    return *reinterpret_cast<unsigned*>(&t);
}

__device__ __forceinline__ void mma_bf16(float* c, const unsigned* a, const unsigned* b) {
    asm volatile(
        "mma.sync.aligned.m16n8k16.row.col.f32.bf16.bf16.f32 "
        "{%0,%1,%2,%3}, {%4,%5,%6,%7}, {%8,%9}, {%0,%1,%2,%3};"
        : "+f"(c[0]), "+f"(c[1]), "+f"(c[2]), "+f"(c[3])
        : "r"(a[0]), "r"(a[1]), "r"(a[2]), "r"(a[3]), "r"(b[0]), "r"(b[1]));
}

__device__ __forceinline__ void ldsm4(unsigned* r, uint32_t addr) {
    asm volatile("ldmatrix.sync.aligned.m8n8.x4.shared.b16 {%0,%1,%2,%3}, [%4];"
        : "=r"(r[0]), "=r"(r[1]), "=r"(r[2]), "=r"(r[3]) : "r"(addr));
}

__device__ __forceinline__ uint32_t s2u(const void* p) {
    return (uint32_t)__cvta_generic_to_shared(p);
}

__device__ __forceinline__ void cpa16(uint32_t dst, const void* src, bool pred) {
    asm volatile("cp.async.ca.shared.global [%0], [%1], 16, %2;"
        :: "r"(dst), "l"(src), "r"(pred ? 16 : 0));
}
#define CP_COMMIT asm volatile("cp.async.commit_group;")
template<int N> __device__ __forceinline__ void cp_wait() {
    asm volatile("cp.async.wait_group %0;" :: "n"(N));
}

__device__ __forceinline__ float sigm(float x) { return 1.f / (1.f + expf(-x)); }

// ---------------- fused f32 -> bf16 conversion (9 segments, 1 launch) -------
struct Cvt9 {
    const float* s[9];
    bf16*        d[9];
    long         off[10];   // prefix offsets in elements; off[9] = total
};

__global__ void f2b_all(Cvt9 P) {
    long i = ((long)blockIdx.x * blockDim.x + threadIdx.x) * 4;
    if (i >= P.off[9]) return;
    int k = 0;
    #pragma unroll
    for (int j = 1; j < 9; j++) if (i >= P.off[j]) k = j;
    long li = i - P.off[k];
    float4 v = *(const float4*)(P.s[k] + li);
    unsigned* du = (unsigned*)(P.d[k] + li);
    du[0] = pk2(v.x, v.y);
    du[1] = pk2(v.z, v.w);
}

// ---------------- bf16 GEMM, cp.async 2-stage pipeline ----------------------
struct GemmB {
    const bf16* A;  int lda;  const int* aidx;
    const bf16* B;  int ldb;
    float*      C;  int ldc;
    bf16*       Cb; int ldcb;
    const float* bias1; const float* bias2;
    int M, N, K;
    int act;
};

__device__ __forceinline__ void gstoreB(const GemmB& p, int m, int n, float v) {
    if (m < p.M && n < p.N) {
        if (p.bias1) v += p.bias1[n];
        if (p.bias2) v += p.bias2[n];
        if (p.act) v = tanhf(v);
        if (p.C)  p.C [(long)m * p.ldc  + n] = v;
        if (p.Cb) p.Cb[(long)m * p.ldcb + n] = __float2bfloat16(v);
    }
}

// BK = 32 elements (64B/row), BKU=16 uints, BKP=20 (16B-aligned stride).
template<int BM, int BN, int WRM, int WRN>
__global__ void __launch_bounds__(WRM*WRN*32)
gemm_k(GemmB P0, GemmB P1) {
    const GemmB p = (blockIdx.z == 0) ? P0 : P1;
    constexpr int THREADS = WRM * WRN * 32;
    constexpr int BKP = 20;
    constexpr int WM = BM / WRM, WN = BN / WRN;
    constexpr int MT = WM / 16, NT = WN / 8;
    static_assert(NT % 2 == 0, "NT even");

    __shared__ unsigned smem[2*BM*BKP + 2*BN*BKP];
    __shared__ int sIdxA[BM];

    const int tid  = threadIdx.x;
    const int warp = tid >> 5, lane = tid & 31;
    const int g = lane >> 2, tig = lane & 3;
    const int wm = warp % WRM, wn = warp / WRM;
    const int bm0 = blockIdx.y * BM, bn0 = blockIdx.x * BN;

    const uint32_t su = s2u(smem);
    const int l8  = lane & 7;
    const int lh8 = (lane >> 3) & 1;
    const int lh16 = lane >> 4;

    for (int r = tid; r < BM; r += THREADS) {
        int m = bm0 + r;
        sIdxA[r] = (m < p.M) ? (p.aidx ? p.aidx[m] : m) : 0;
    }
    __syncthreads();

    float acc[MT][NT][4];
    #pragma unroll
    for (int mt = 0; mt < MT; mt++)
        #pragma unroll
        for (int nt = 0; nt < NT; nt++)
            #pragma unroll
            for (int q = 0; q < 4; q++) acc[mt][nt][q] = 0.f;

    auto issue = [&](int st, int k0) {
        #pragma unroll 2
        for (int c = tid; c < BM * 4; c += THREADS) {
            int r = c >> 2, off = c & 3;
            uint32_t dst = su + (uint32_t)(st * BM * BKP + r * BKP + off * 4) * 4u;
            cpa16(dst, p.A + (long)sIdxA[r] * p.lda + k0 + off * 8, bm0 + r < p.M);
        }
        #pragma unroll 2
        for (int c = tid; c < BN * 4; c += THREADS) {
            int r = c >> 2, off = c & 3;
            int n = bn0 + r;
            bool ok = n < p.N;
            uint32_t dst = su + (uint32_t)(2*BM*BKP + st * BN * BKP + r * BKP + off * 4) * 4u;
            cpa16(dst, p.B + (long)(ok ? n : 0) * p.ldb + k0 + off * 8, ok);
        }
        CP_COMMIT;
    };

    const int KT = p.K >> 5;
    issue(0, 0);
    for (int kt = 0; kt < KT; kt++) {
        const int st = kt & 1;
        if (kt + 1 < KT) { issue(st ^ 1, (kt + 1) << 5); cp_wait<1>(); }
        else             { cp_wait<0>(); }
        __syncthreads();

        const uint32_t aBase = su + (uint32_t)(st * BM * BKP) * 4u;
        const uint32_t bBase = su + (uint32_t)(2*BM*BKP + st * BN * BKP) * 4u;
        #pragma unroll
        for (int ku = 0; ku < 16; ku += 8) {
            unsigned afr[MT][4];
            unsigned bfr[NT][2];
            #pragma unroll
            for (int mt = 0; mt < MT; mt++) {
                int mb = wm * WM + mt * 16;
                ldsm4(afr[mt], aBase + (uint32_t)((mb + lh8*8 + l8) * BKP + ku + lh16*4) * 4u);
            }
            #pragma unroll
            for (int nt = 0; nt < NT; nt += 2) {
                int nb = wn * WN + nt * 8;
                unsigned r[4];
                ldsm4(r, bBase + (uint32_t)((nb + lh16*8 + l8) * BKP + ku + lh8*4) * 4u);
                bfr[nt][0] = r[0]; bfr[nt][1] = r[1];
                bfr[nt+1][0] = r[2]; bfr[nt+1][1] = r[3];
            }
            #pragma unroll
            for (int mt = 0; mt < MT; mt++)
                #pragma unroll
                for (int nt = 0; nt < NT; nt++)
                    mma_bf16(acc[mt][nt], afr[mt], bfr[nt]);
        }
        __syncthreads();
    }

    #pragma unroll
    for (int mt = 0; mt < MT; mt++) {
        int r0 = bm0 + wm * WM + mt * 16 + g;
        #pragma unroll
        for (int nt = 0; nt < NT; nt++) {
            int c0 = bn0 + wn * WN + nt * 8 + 2 * tig;
            gstoreB(p, r0,     c0,     acc[mt][nt][0]);
            gstoreB(p, r0,     c0 + 1, acc[mt][nt][1]);
            gstoreB(p, r0 + 8, c0,     acc[mt][nt][2]);
            gstoreB(p, r0 + 8, c0 + 1, acc[mt][nt][3]);
        }
    }
}

// ---------------- persistent recurrence kernel ------------------------------
// grid = (8, 4, 2) = 64 blocks <= 148 SMs -> all co-resident (wave 1), so a
// software global barrier is deadlock-free. t-loop inside; barrier target
// 64*t on monotonic counter g_bar (zeroed via cudaMemsetAsync per launch).
__global__ void __launch_bounds__(256) steps_persist(
    bf16* HCB, const int* FIDX, const int* SIDX,
    const bf16* AWHH, const bf16* FWHH,
    const float* XA, const float* XF,
    float* CS, float* BC)
{
    const int cell = blockIdx.z;
    const int u0 = blockIdx.x * 64;
    const int b0 = blockIdx.y * 32;

    const bf16*  W  = cell ? FWHH : AWHH;
    const float* X  = cell ? XF : XA;
    const float* Cp = cell ? BC : CS;
    float*       Co = cell ? BC : CS;
    const bf16*  Ab = HCB + (cell ? HID : 0);
    bf16*        Hb = HCB + (cell ? HID : 0);
    const int*   IDX = cell ? SIDX : FIDX;

    __shared__ unsigned smem[2*32*20 + 2*256*20];   // 46080 B
    float (*sG)[260] = (float(*)[260])smem;
    __shared__ int sIdx[32];

    const int tid  = threadIdx.x;
    const int warp = tid >> 5, lane = tid & 31;
    const int g = lane >> 2, tig = lane & 3;
    const int wm = warp & 1, wn = warp >> 1;    // 2x4 warps; WM=16, WN=64

    const uint32_t su = s2u(smem);
    const int l8  = lane & 7;
    const int lh8 = (lane >> 3) & 1;
    const int lh16 = lane >> 4;

    for (int t = 1; t < SEQ; t++) {
        const bool skip = cell && ((t - 1) % 3 == 0);   // reset: f-cell prewritten
        if (!skip) {
            if (tid < 32) sIdx[tid] = IDX[t * BATCH + b0 + tid];
            __syncthreads();

            float acc[8][4];
            #pragma unroll
            for (int nt = 0; nt < 8; nt++)
                #pragma unroll
                for (int q = 0; q < 4; q++) acc[nt][q] = 0.f;

            auto issue = [&](int st, int k0) {
                if (tid < 128) {               // A: 32 rows x 4 chunks
                    int r = tid >> 2, off = tid & 3;
                    uint32_t dst = su + (uint32_t)(st * 640 + r * 20 + off * 4) * 4u;
                    cpa16(dst, Ab + (long)sIdx[r] * (2*HID) + k0 + off * 8, true);
                }
                #pragma unroll
                for (int c = tid; c < 1024; c += 256) {   // B: 256 rows x 4 chunks
                    int r = c >> 2, off = c & 3;
                    int wrow = (r >> 6) * HID + u0 + (r & 63);
                    uint32_t dst = su + (uint32_t)(1280 + st * 5120 + r * 20 + off * 4) * 4u;
                    cpa16(dst, W + (long)wrow * HID + k0 + off * 8, true);
                }
                CP_COMMIT;
            };

            issue(0, 0);
            #pragma unroll 1
            for (int kt = 0; kt < 16; kt++) {
                const int st = kt & 1;
                if (kt + 1 < 16) { issue(st ^ 1, (kt + 1) << 5); cp_wait<1>(); }
                else             { cp_wait<0>(); }
                __syncthreads();

                const uint32_t aBase = su + (uint32_t)(st * 640) * 4u;
                const uint32_t bBase = su + (uint32_t)(1280 + st * 5120) * 4u;
                #pragma unroll
                for (int ku = 0; ku < 16; ku += 8) {
                    unsigned afr[4];
                    {
                        int mb = wm * 16;
                        ldsm4(afr, aBase + (uint32_t)((mb + lh8*8 + l8) * 20 + ku + lh16*4) * 4u);
                    }
                    unsigned bfr[8][2];
                    #pragma unroll
                    for (int nt = 0; nt < 8; nt += 2) {
                        int nb = wn * 64 + nt * 8;
                        unsigned r[4];
                        ldsm4(r, bBase + (uint32_t)((nb + lh16*8 + l8) * 20 + ku + lh8*4) * 4u);
                        bfr[nt][0] = r[0]; bfr[nt][1] = r[1];
                        bfr[nt+1][0] = r[2]; bfr[nt+1][1] = r[3];
                    }
                    #pragma unroll
                    for (int nt = 0; nt < 8; nt++)
                        mma_bf16(acc[nt], afr, bfr[nt]);
                }
                __syncthreads();
            }

            // stage gates to shared (overlays pipeline buffers)
            #pragma unroll
            for (int nt = 0; nt < 8; nt++) {
                const int m = wm * 16 + g;
                const int n = wn * 64 + nt * 8 + 2 * tig;
                sG[m    ][n    ] = acc[nt][0];
                sG[m    ][n + 1] = acc[nt][1];
                sG[m + 8][n    ] = acc[nt][2];
                sG[m + 8][n + 1] = acc[nt][3];
            }
            __syncthreads();

            #pragma unroll
            for (int e = tid; e < 2048; e += 256) {
                const int m = e >> 6, ul = e & 63;
                const int b = b0 + m, u = u0 + ul;
                const long xr = sIdx[m];
                const float* xp = X + xr * (long)GATE4;
                float gi = sG[m][ul      ] + xp[u            ];
                float gf = sG[m][64 + ul ] + xp[HID + u      ];
                float gg = sG[m][128 + ul] + xp[2 * HID + u  ];
                float go = sG[m][192 + ul] + xp[3 * HID + u  ];
                float cp = Cp[xr * HID + u];
                float c2 = sigm(gf) * cp + sigm(gi) * tanhf(gg);
                float h  = sigm(go) * tanhf(c2);
                Hb[(long)t * (2*HID) + (long)b * (SEQ * 2 * HID) + u] = __float2bfloat16(h);
                Co[(long)t * HID     + (long)b * (SEQ * HID)     + u] = c2;
            }
        }

        // global barrier: all 64 blocks arrive; target = 64*t (monotonic)
        __threadfence();
        __syncthreads();
        if (tid == 0) {
            atomicAdd(&g_bar, 1u);
            volatile unsigned* vb = &g_bar;
            while (*vb < 64u * (unsigned)t) __nanosleep(64);
        }
        __syncthreads();
    }
}

// ---------------- sibling reset: t-invariant, all 13 reset slots at once ----
__global__ void sib_reset_all(const float* fb1, const float* fb2) {
    int i = blockIdx.x * blockDim.x + threadIdx.x;
    if (i >= BATCH * HID) return;
    int b = i >> 9, u = i & (HID - 1);
    float fi = fb1[u]         + fb2[u];
    float fg = fb1[2*HID + u] + fb2[2*HID + u];
    float fo = fb1[3*HID + u] + fb2[3*HID + u];
    float bc2 = sigm(fi) * tanhf(fg);       // cprev = 0
    bf16 bhb = __float2bfloat16(sigm(fo) * tanhf(bc2));
    #pragma unroll
    for (int t = 1; t < SEQ; t += 3) {      // (t-1)%3==0 -> t = 1,4,...,37
        long orow = (long)b * SEQ + t;
        g_HCATB[orow * (2 * HID) + HID + u] = bhb;
        g_BC[orow * HID + u] = bc2;
    }
}

// ---------------- index dtype sniff + normalization -------------------------
__global__ void sniff_idx(const int* word32) {
    if (threadIdx.x == 0) {
        int allzero = 1;
        for (int i = 0; i < 64; i++)
            if (word32[2 * i + 1] != 0) { allzero = 0; break; }
        g_IS64 = allzero;
    }
}

__global__ void prep_idx(const int* word32, const int* father32) {
    int i = blockIdx.x * blockDim.x + threadIdx.x;
    if (i >= MTOT) return;
    int is64 = g_IS64;
    int w = is64 ? word32[2 * i]   : word32[i];
    int f = is64 ? father32[2 * i] : father32[i];
    g_WIDX[i] = w;
    int t = i % SEQ, b = i / SEQ;
    g_FIDX[t * BATCH + b] = b * SEQ + f;
    g_SIDX[t * BATCH + b] = b * SEQ + (t > 0 ? t - 1 : 0);
}

// ---------------- step-0 LSTM elementwise -----------------------------------
__global__ void lstm_ew0(const float* fb1, const float* fb2) {
    int i = blockIdx.x * blockDim.x + threadIdx.x;
    if (i >= BATCH * HID) return;
    int b = i >> 9, u = i & (HID - 1);
    const float* ga = g_GATES + (long)b * (2 * GATE4);
    float gi = ga[u], gg = ga[2*HID + u], go = ga[3*HID + u];
    float c2 = sigm(gi) * tanhf(gg);
    float ch = sigm(go) * tanhf(c2);
    long orow = (long)b * SEQ;
    g_HCATB[orow * (2 * HID) + u] = __float2bfloat16(ch);
    g_CS[orow * HID + u] = c2;
    float fi = fb1[u]         + fb2[u];
    float fg = fb1[2*HID + u] + fb2[2*HID + u];
    float fo = fb1[3*HID + u] + fb2[3*HID + u];
    float bc2 = sigm(fi) * tanhf(fg);
    float bh  = sigm(fo) * tanhf(bc2);
    g_HCATB[orow * (2 * HID) + HID + u] = __float2bfloat16(bh);
    g_BC[orow * HID + u] = bc2;
}

// ---------------- in-place log_softmax over rows of 10000 -------------------
__global__ void logsoftmax_k(float* out) {
    const long row = blockIdx.x;
    float* p = out + row * (long)VOC;
    const int tid = threadIdx.x;
    __shared__ float sred[8];

    float v[40];
    float mx = -INFINITY;
    #pragma unroll
    for (int j = 0; j < 40; j++) {
        int idx = j * 256 + tid;
        v[j] = (idx < VOC) ? p[idx] : -INFINITY;
        mx = fmaxf(mx, v[j]);
    }
    #pragma unroll
    for (int o = 16; o > 0; o >>= 1)
        mx = fmaxf(mx, __shfl_xor_sync(0xffffffffu, mx, o));
    if ((tid & 31) == 0) sred[tid >> 5] = mx;
    __syncthreads();
    float mall = -INFINITY;
    #pragma unroll
    for (int w = 0; w < 8; w++) mall = fmaxf(mall, sred[w]);
    __syncthreads();

    float s = 0.f;
    #pragma unroll
    for (int j = 0; j < 40; j++) {
        int idx = j * 256 + tid;
        if (idx < VOC) s += expf(v[j] - mall);
    }
    #pragma unroll
    for (int o = 16; o > 0; o >>= 1)
        s += __shfl_xor_sync(0xffffffffu, s, o);
    if ((tid & 31) == 0) sred[tid >> 5] = s;
    __syncthreads();
    float stot = 0.f;
    #pragma unroll
    for (int w = 0; w < 8; w++) stot += sred[w];

    float lse = mall + logf(stot);
    #pragma unroll
    for (int j = 0; j < 40; j++) {
        int idx = j * 256 + tid;
        if (idx < VOC) p[idx] = v[j] - lse;
    }
}

// ---------------- host orchestration ---------------------------------------
extern "C" void kernel_launch(void* const* d_in, const int* in_sizes, int n_in,
                              void* d_out, int out_size) {
    const int*   word    = (const int*)  d_in[0];
    const int*   father  = (const int*)  d_in[1];
    const float* fc_feats= (const float*)d_in[2];
    const float* embed   = (const float*)d_in[3];
    const float* fc_w    = (const float*)d_in[4];
    const float* fc_b    = (const float*)d_in[5];
    const float* a_wih   = (const float*)d_in[6];
    const float* a_whh   = (const float*)d_in[7];
    const float* a_bih   = (const float*)d_in[8];
    const float* a_bhh   = (const float*)d_in[9];
    const float* f_wih   = (const float*)d_in[10];
    const float* f_whh   = (const float*)d_in[11];
    const float* f_bih   = (const float*)d_in[12];
    const float* f_bhh   = (const float*)d_in[13];
    const float* pred_w  = (const float*)d_in[14];
    const float* pred_b  = (const float*)d_in[15];
    const float* logit_w = (const float*)d_in[16];
    const float* logit_b = (const float*)d_in[17];
    float* out = (float*)d_out;

    float *XA, *XF, *GT, *CS, *BC;
    int *FIDX, *SIDX, *WIDX;
    unsigned* BAR;
    bf16 *EMBB, *AWIH, *FWIH, *AWHH, *FWHH, *PREDW, *LOGW, *FCW, *FCFB, *X0B, *HCB, *OUTB;
    cudaGetSymbolAddress((void**)&XA,  g_XA);
    cudaGetSymbolAddress((void**)&XF,  g_XF);
    cudaGetSymbolAddress((void**)&GT,  g_GATES);
    cudaGetSymbolAddress((void**)&CS,  g_CS);
    cudaGetSymbolAddress((void**)&BC,  g_BC);
    cudaGetSymbolAddress((void**)&FIDX, g_FIDX);
    cudaGetSymbolAddress((void**)&SIDX, g_SIDX);
    cudaGetSymbolAddress((void**)&WIDX, g_WIDX);
    cudaGetSymbolAddress((void**)&BAR,  g_bar);
    cudaGetSymbolAddress((void**)&EMBB, g_EMBB);
    cudaGetSymbolAddress((void**)&AWIH, g_AWIH);
    cudaGetSymbolAddress((void**)&FWIH, g_FWIH);
    cudaGetSymbolAddress((void**)&AWHH, g_AWHH);
    cudaGetSymbolAddress((void**)&FWHH, g_FWHH);
    cudaGetSymbolAddress((void**)&PREDW, g_PREDW);
    cudaGetSymbolAddress((void**)&LOGW, g_LOGW);
    cudaGetSymbolAddress((void**)&FCW,  g_FCW);
    cudaGetSymbolAddress((void**)&FCFB, g_FCFB);
    cudaGetSymbolAddress((void**)&X0B,  g_X0B);
    cudaGetSymbolAddress((void**)&HCB,  g_HCATB);
    cudaGetSymbolAddress((void**)&OUTB, g_OUTB);

    cudaMemsetAsync(BAR, 0, sizeof(unsigned));
    sniff_idx<<<1, 32>>>(word);
    prep_idx<<<(MTOT + 255) / 256, 256>>>(word, father);

    // one-shot fused f32 -> bf16 conversion (9 segments)
    {
        Cvt9 P{};
        const float* ss[9] = {embed, a_wih, f_wih, a_whh, f_whh, pred_w, logit_w, fc_w, fc_feats};
        bf16* dd[9] = {EMBB, AWIH, FWIH, AWHH, FWHH, PREDW, LOGW, FCW, FCFB};
        long nn[9] = {(long)VOC*EMB, (long)GATE4*EMB, (long)GATE4*EMB,
                      (long)GATE4*HID, (long)GATE4*HID, (long)HID*2*HID,
                      (long)VOC*HID, (long)EMB*FCF, (long)BATCH*FCF};
        long acc = 0;
        for (int k = 0; k < 9; k++) { P.s[k] = ss[k]; P.d[k] = dd[k]; P.off[k] = acc; acc += nn[k]; }
        P.off[9] = acc;
        long thr = acc / 4;
        f2b_all<<<(int)((thr + 255) / 256), 256>>>(P);
    }

    // X0B = bf16(fc_feats @ fc_w^T + fc_b)     [128, 512], K=2048
    {
        GemmB p{}; p.A = FCFB; p.lda = FCF; p.B = FCW; p.ldb = FCF;
        p.Cb = X0B; p.ldcb = EMB; p.bias1 = fc_b;
        p.M = BATCH; p.N = EMB; p.K = FCF;
        gemm_k<32,64,1,2><<<dim3(EMB/64, BATCH/32, 1), 64>>>(p, p);
    }
    // XA/XF = embed[word] @ {a,f}_wih^T + biases   [5120, 2048], K=512 (z=2)
    {
        GemmB pa{}; pa.A = EMBB; pa.lda = EMB; pa.aidx = WIDX;
        pa.B = AWIH; pa.ldb = EMB; pa.C = XA; pa.ldc = GATE4;
        pa.bias1 = a_bih; pa.bias2 = a_bhh;
        pa.M = MTOT; pa.N = GATE4; pa.K = EMB;
        GemmB pf = pa;
        pf.B = FWIH; pf.C = XF; pf.bias1 = f_bih; pf.bias2 = f_bhh;
        gemm_k<128,128,4,2><<<dim3(GATE4/128, MTOT/128, 2), 256>>>(pa, pf);
    }
    // step 0 a-gates: GT = X0 @ a_wih^T + a_bih + a_bhh
    {
        GemmB p{}; p.A = X0B; p.lda = EMB; p.B = AWIH; p.ldb = EMB;
        p.C = GT; p.ldc = 2 * GATE4; p.bias1 = a_bih; p.bias2 = a_bhh;
        p.M = BATCH; p.N = GATE4; p.K = EMB;
        gemm_k<32,64,1,2><<<dim3(GATE4/64, BATCH/32, 1), 64>>>(p, p);
    }
    lstm_ew0<<<(BATCH * HID + 255) / 256, 256>>>(f_bih, f_bhh);
    sib_reset_all<<<(BATCH * HID + 255) / 256, 256>>>(f_bih, f_bhh);

    // persistent recurrence: all 39 steps in ONE launch (64 co-resident blocks)
    steps_persist<<<dim3(HID/64, BATCH/32, 2), 256>>>(
        HCB, FIDX, SIDX, AWHH, FWHH, XA, XF, CS, BC);

    // OUTB = bf16(tanh(HCATB @ pred_w^T + pred_b))   [5120, 512], K=1024
    {
        GemmB p{}; p.A = HCB; p.lda = 2 * HID; p.B = PREDW; p.ldb = 2 * HID;
        p.Cb = OUTB; p.ldcb = HID; p.bias1 = pred_b; p.act = 1;
        p.M = MTOT; p.N = HID; p.K = 2 * HID;
        gemm_k<128,128,4,2><<<dim3(HID/128, MTOT/128, 1), 256>>>(p, p);
    }
    // d_out = OUTB @ logit_w^T + logit_b        [5120, 10000], K=512
    {
        GemmB p{}; p.A = OUTB; p.lda = HID; p.B = LOGW; p.ldb = HID;
        p.C = out; p.ldc = VOC; p.bias1 = logit_b;
        p.M = MTOT; p.N = VOC; p.K = HID;
        gemm_k<128,128,4,2><<<dim3((VOC + 127) / 128, MTOT/128, 1), 256>>>(p, p);
    }
    logsoftmax_k<<<MTOT, 256>>>(out);
}